// round 12
// baseline (speedup 1.0000x reference)
#include <cuda_runtime.h>
#include <cuda_bf16.h>
#include <cuda_fp16.h>
#include <cstdint>
#include <math.h>

#define S_LEN  4096
#define DMODEL 1024
#define NHEADS 16
#define DK     64

// ======================= scratch (device globals) =======================
__device__ int8_t g_x1[(size_t)S_LEN * DMODEL];
__device__ int8_t g_x2[(size_t)S_LEN * DMODEL];
__device__ float  g_sx[S_LEN];

__device__ int8_t g_wq1[(size_t)DMODEL * DMODEL];
__device__ int8_t g_wq2[(size_t)DMODEL * DMODEL];
__device__ int8_t g_wk1[(size_t)DMODEL * DMODEL];
__device__ int8_t g_wk2[(size_t)DMODEL * DMODEL];
__device__ int8_t g_wv1[(size_t)DMODEL * DMODEL];
__device__ int8_t g_wv2[(size_t)DMODEL * DMODEL];
__device__ int8_t g_wo1[(size_t)DMODEL * DMODEL];
__device__ int8_t g_wo2[(size_t)DMODEL * DMODEL];
__device__ unsigned g_wbits[4 * DMODEL];

// attention operands
__device__ int8_t g_q1[(size_t)S_LEN * DMODEL];
__device__ int8_t g_q2[(size_t)S_LEN * DMODEL];
__device__ int8_t g_k1[(size_t)S_LEN * DMODEL];
__device__ int8_t g_k2[(size_t)S_LEN * DMODEL];
__device__ float  g_sq[NHEADS * S_LEN];
__device__ float  g_sk[NHEADS * S_LEN];
__device__ __half g_v16[(size_t)S_LEN * DMODEL];

__device__ float  g_ctx[(size_t)S_LEN * DMODEL];
__device__ int8_t g_c1[(size_t)S_LEN * DMODEL];
__device__ int8_t g_c2[(size_t)S_LEN * DMODEL];
__device__ float  g_sc[S_LEN];

// ======================= helpers =======================
__device__ __forceinline__ uint32_t smem_u32(const void* p) {
    uint32_t a;
    asm("{ .reg .u64 t; cvta.to.shared.u64 t, %1; cvt.u32.u64 %0, t; }" : "=r"(a) : "l"(p));
    return a;
}
__device__ __forceinline__ void cp16(uint32_t saddr, const void* g) {
    asm volatile("cp.async.ca.shared.global [%0], [%1], 16;" :: "r"(saddr), "l"(g));
}
__device__ __forceinline__ void cp_commit() { asm volatile("cp.async.commit_group;"); }
__device__ __forceinline__ void cp_wait1()  { asm volatile("cp.async.wait_group 1;"); }
__device__ __forceinline__ void cp_wait0()  { asm volatile("cp.async.wait_group 0;"); }

__device__ __forceinline__ void ldsm_x4(uint32_t* r, uint32_t addr) {
    asm volatile("ldmatrix.sync.aligned.m8n8.x4.shared.b16 {%0,%1,%2,%3}, [%4];"
                 : "=r"(r[0]), "=r"(r[1]), "=r"(r[2]), "=r"(r[3]) : "r"(addr));
}
__device__ __forceinline__ void ldsm_x4_t(uint32_t* r, uint32_t addr) {
    asm volatile("ldmatrix.sync.aligned.m8n8.x4.trans.shared.b16 {%0,%1,%2,%3}, [%4];"
                 : "=r"(r[0]), "=r"(r[1]), "=r"(r[2]), "=r"(r[3]) : "r"(addr));
}
__device__ __forceinline__ void mma_s8(int* c, const uint32_t* a, const uint32_t* b) {
    asm volatile(
        "mma.sync.aligned.m16n8k32.row.col.s32.s8.s8.s32 "
        "{%0,%1,%2,%3}, {%4,%5,%6,%7}, {%8,%9}, {%0,%1,%2,%3};"
        : "+r"(c[0]), "+r"(c[1]), "+r"(c[2]), "+r"(c[3])
        : "r"(a[0]), "r"(a[1]), "r"(a[2]), "r"(a[3]), "r"(b[0]), "r"(b[1]));
}
__device__ __forceinline__ void mma_f16(float* c, const uint32_t* a, const uint32_t* b) {
    asm volatile(
        "mma.sync.aligned.m16n8k16.row.col.f32.f16.f16.f32 "
        "{%0,%1,%2,%3}, {%4,%5,%6,%7}, {%8,%9}, {%0,%1,%2,%3};"
        : "+f"(c[0]), "+f"(c[1]), "+f"(c[2]), "+f"(c[3])
        : "r"(a[0]), "r"(a[1]), "r"(a[2]), "r"(a[3]), "r"(b[0]), "r"(b[1]));
}
__device__ __forceinline__ float ex2f(float x) {
    float y;
    asm("ex2.approx.f32 %0, %1;" : "=f"(y) : "f"(x));
    return y;
}
__device__ __forceinline__ uint32_t h2u(float x, float y) {
    __half2 h = __floats2half2_rn(x, y);
    return *(uint32_t*)&h;
}
__device__ __forceinline__ void digits2(float alpha, int& d1, int& d2) {
    d1 = __float2int_rn(alpha);
    d2 = __float2int_rn((alpha - (float)d1) * 254.f);
}
__device__ __forceinline__ uint32_t pack_dig(float a, float b, uint32_t& w2) {
    int a1, a2, b1, b2;
    digits2(a, a1, a2);
    digits2(b, b1, b2);
    w2 = (uint32_t)(a2 & 0xff) | (((uint32_t)(b2 & 0xff)) << 8);
    return (uint32_t)(a1 & 0xff) | (((uint32_t)(b1 & 0xff)) << 8);
}
__device__ __forceinline__ uint32_t pack4b(int a, int b, int c, int d) {
    return (uint32_t)(a & 0xff) | (((uint32_t)(b & 0xff)) << 8) |
           (((uint32_t)(c & 0xff)) << 16) | (((uint32_t)(d & 0xff)) << 24);
}

// ======================= weight prep (parallelized) =======================
__global__ __launch_bounds__(1024)
void colmax4_kernel(const float* __restrict__ Wq, const float* __restrict__ Wk,
                    const float* __restrict__ Wv, const float* __restrict__ Wo)
{
    const int z = blockIdx.y;
    const float* W = (z == 0) ? Wq : (z == 1) ? Wk : (z == 2) ? Wv : Wo;
    unsigned* bits = g_wbits + z * DMODEL;

    const int tid  = threadIdx.x;
    const int col  = blockIdx.x * 128 + (tid & 127);
    const int part = tid >> 7;

    float m = 0.f;
    #pragma unroll 8
    for (int r = part; r < DMODEL; r += 8)
        m = fmaxf(m, fabsf(W[(size_t)r * DMODEL + col]));

    __shared__ float red[8][128];
    red[part][tid & 127] = m;
    __syncthreads();
    if (tid < 128) {
        float mm = red[0][tid];
        #pragma unroll
        for (int i = 1; i < 8; ++i) mm = fmaxf(mm, red[i][tid]);
        bits[blockIdx.x * 128 + tid] = __float_as_uint(fmaxf(mm, 1e-30f));
    }
}

__global__ __launch_bounds__(256)
void transpose_quant4_kernel(const float* __restrict__ W0, const float* __restrict__ W1,
                             const float* __restrict__ W2, const float* __restrict__ W3)
{
    const int z = blockIdx.z;
    const float* W = (z == 0) ? W0 : (z == 1) ? W1 : (z == 2) ? W2 : W3;
    int8_t* B1 = (z == 0) ? g_wq1 : (z == 1) ? g_wk1 : (z == 2) ? g_wv1 : g_wo1;
    int8_t* B2 = (z == 0) ? g_wq2 : (z == 1) ? g_wk2 : (z == 2) ? g_wv2 : g_wo2;
    const unsigned* b = g_wbits + z * DMODEL;

    __shared__ float t[32][33];
    const int n0 = blockIdx.x * 32, k0 = blockIdx.y * 32;
    const int lx = threadIdx.x & 31, ly = threadIdx.x >> 5;
    #pragma unroll
    for (int i = 0; i < 32; i += 8)
        t[ly + i][lx] = W[(size_t)(k0 + ly + i) * DMODEL + n0 + lx];
    __syncthreads();
    #pragma unroll
    for (int i = 0; i < 32; i += 8) {
        const int n = n0 + ly + i;
        const float inv = 127.f / __uint_as_float(b[n]);
        int d1, d2;
        digits2(t[lx][ly + i] * inv, d1, d2);
        const size_t o = (size_t)n * DMODEL + k0 + lx;
        B1[o] = (int8_t)d1;
        B2[o] = (int8_t)d2;
    }
}

__global__ __launch_bounds__(256)
void rowquant_kernel(const float* __restrict__ src,
                     int8_t* __restrict__ D1, int8_t* __restrict__ D2,
                     float* __restrict__ s)
{
    const int row = blockIdx.x;
    const int tid = threadIdx.x;
    const float4 v = ((const float4*)(src + (size_t)row * DMODEL))[tid];
    float m = fmaxf(fmaxf(fabsf(v.x), fabsf(v.y)), fmaxf(fabsf(v.z), fabsf(v.w)));
    #pragma unroll
    for (int o = 16; o >= 1; o >>= 1)
        m = fmaxf(m, __shfl_xor_sync(0xffffffffu, m, o));
    __shared__ float red[8];
    if ((tid & 31) == 0) red[tid >> 5] = m;
    __syncthreads();
    float mm = red[0];
    #pragma unroll
    for (int i = 1; i < 8; i++) mm = fmaxf(mm, red[i]);
    mm = fmaxf(mm, 1e-30f);
    if (tid == 0) s[row] = mm * (1.f / 127.f);
    const float inv = 127.f / mm;
    int d1, d2;
    char4 c1, c2;
    digits2(v.x * inv, d1, d2); c1.x = (char)d1; c2.x = (char)d2;
    digits2(v.y * inv, d1, d2); c1.y = (char)d1; c2.y = (char)d2;
    digits2(v.z * inv, d1, d2); c1.z = (char)d1; c2.z = (char)d2;
    digits2(v.w * inv, d1, d2); c1.w = (char)d1; c2.w = (char)d2;
    ((char4*)(D1 + (size_t)row * DMODEL))[tid] = c1;
    ((char4*)(D2 + (size_t)row * DMODEL))[tid] = c2;
}

// ======================= int8 dual-digit GEMM cores =======================
#define QBK 64
#define QNCH (DMODEL / QBK)
#define QROWB 80
#define QARR_B (128 * QROWB)
#define QSTAGE_B (4 * QARR_B)
#define QGEMM_SMEM (2 * QSTAGE_B)

struct GemmAcc { int a1[2][8][4]; int a2[2][8][4]; };

__device__ __forceinline__ void gemm_mainloop(
    const int8_t* A1p, const int8_t* A2p, const int8_t* B1p, const int8_t* B2p,
    char* sm, uint32_t sbase, int tid, int lane, int mw0, int nw0, GemmAcc& acc)
{
    #pragma unroll
    for (int i = 0; i < 2; i++)
        #pragma unroll
        for (int j = 0; j < 8; j++)
            #pragma unroll
            for (int q = 0; q < 4; q++) { acc.a1[i][j][q] = 0; acc.a2[i][j][q] = 0; }

    const int8_t* srcs[4] = { A1p, A2p, B1p, B2p };
    const int a_row = lane & 15;
    const int a_kb  = (lane >> 4) * 16;
    const int b_row = ((lane >> 4) << 3) + (lane & 7);
    const int b_kb  = ((lane >> 3) & 1) * 16;

    auto issue_loads = [&](int c, int stage) {
        const int k0 = c * QBK;
        const uint32_t sb = sbase + stage * QSTAGE_B;
        #pragma unroll
        for (int t = 0; t < 4; t++) {
            #pragma unroll
            for (int jj = 0; jj < 2; jj++) {
                const int slot = tid + jj * 256;
                const int row = slot >> 2, col = slot & 3;
                cp16(sb + t * QARR_B + row * QROWB + col * 16,
                     srcs[t] + (size_t)row * DMODEL + k0 + col * 16);
            }
        }
    };

    issue_loads(0, 0);
    cp_commit();

    for (int c = 0; c < QNCH; ++c) {
        const int stage = c & 1;
        const bool hasNext = (c + 1 < QNCH);
        if (hasNext) { issue_loads(c + 1, stage ^ 1); cp_commit(); }
        if (hasNext) cp_wait1(); else cp_wait0();
        __syncthreads();

        const uint32_t sb = sbase + stage * QSTAGE_B;
        #pragma unroll
        for (int ks = 0; ks < 2; ++ks) {
            const int kb = ks * 32;
            uint32_t fa1[2][4], fa2[2][4];
            #pragma unroll
            for (int mi = 0; mi < 2; ++mi) {
                const uint32_t aoff = (uint32_t)(mw0 + mi * 16 + a_row) * QROWB + kb + a_kb;
                ldsm_x4(fa1[mi], sb + 0 * QARR_B + aoff);
                ldsm_x4(fa2[mi], sb + 1 * QARR_B + aoff);
            }
            #pragma unroll
            for (int nt2 = 0; nt2 < 4; ++nt2) {
                const uint32_t boff = (uint32_t)(nw0 + nt2 * 16 + b_row) * QROWB + kb + b_kb;
                uint32_t fb1[4], fb2[4];
                ldsm_x4(fb1, sb + 2 * QARR_B + boff);
                ldsm_x4(fb2, sb + 3 * QARR_B + boff);
                #pragma unroll
                for (int mi = 0; mi < 2; ++mi) {
                    #pragma unroll
                    for (int half = 0; half < 2; ++half) {
                        mma_s8(acc.a1[mi][nt2 * 2 + half], fa1[mi], fb1 + half * 2);
                        mma_s8(acc.a2[mi][nt2 * 2 + half], fa1[mi], fb2 + half * 2);
                        mma_s8(acc.a2[mi][nt2 * 2 + half], fa2[mi], fb1 + half * 2);
                    }
                }
            }
        }
        __syncthreads();
    }
}

// fused Q/K/V projection: grid (8, 32, 3), 2 CTAs/SM
__global__ __launch_bounds__(256, 2)
void gemm_qkv_kernel(const float* __restrict__ bq,
                     const float* __restrict__ bk,
                     const float* __restrict__ bv)
{
    extern __shared__ char sm[];
    const uint32_t sbase = smem_u32(sm);
    const int tid  = threadIdx.x;
    const int lane = tid & 31;
    const int wid  = tid >> 5;
    const int mw0  = (wid & 3) * 32;
    const int nw0  = (wid >> 2) * 64;
    const int bm   = blockIdx.y * 128;
    const int bn   = blockIdx.x * 128;
    const int z    = blockIdx.z;

    const int8_t* B1 = (z == 0) ? g_wq1 : (z == 1) ? g_wk1 : g_wv1;
    const int8_t* B2 = (z == 0) ? g_wq2 : (z == 1) ? g_wk2 : g_wv2;
    const float* bias = (z == 0) ? bq : (z == 1) ? bk : bv;
    const unsigned* sBbits = g_wbits + z * DMODEL;

    GemmAcc acc;
    gemm_mainloop(g_x1 + (size_t)bm * DMODEL, g_x2 + (size_t)bm * DMODEL,
                  B1 + (size_t)bn * DMODEL, B2 + (size_t)bn * DMODEL,
                  sm, sbase, tid, lane, mw0, nw0, acc);

    const int erow = lane >> 2;
    const int ecol = (lane & 3) * 2;
    const float* sA = g_sx;

    if (z == 2) {
        #pragma unroll
        for (int mi = 0; mi < 2; ++mi) {
            const int m0 = bm + mw0 + mi * 16 + erow;
            const float sa0 = sA[m0], sa8 = sA[m0 + 8];
            #pragma unroll
            for (int ni = 0; ni < 8; ++ni) {
                const int n = bn + nw0 + ni * 8 + ecol;
                const float sb0 = __uint_as_float(sBbits[n])     * (1.f / 127.f);
                const float sb1 = __uint_as_float(sBbits[n + 1]) * (1.f / 127.f);
                const float b0 = bias[n], b1 = bias[n + 1];
                const float c00 = ((float)acc.a1[mi][ni][0] + (float)acc.a2[mi][ni][0] * (1.f / 254.f)) * (sa0 * sb0) + b0;
                const float c01 = ((float)acc.a1[mi][ni][1] + (float)acc.a2[mi][ni][1] * (1.f / 254.f)) * (sa0 * sb1) + b1;
                const float c10 = ((float)acc.a1[mi][ni][2] + (float)acc.a2[mi][ni][2] * (1.f / 254.f)) * (sa8 * sb0) + b0;
                const float c11 = ((float)acc.a1[mi][ni][3] + (float)acc.a2[mi][ni][3] * (1.f / 254.f)) * (sa8 * sb1) + b1;
                *(uint32_t*)(g_v16 + (size_t)m0 * DMODEL + n)       = h2u(c00, c01);
                *(uint32_t*)(g_v16 + (size_t)(m0 + 8) * DMODEL + n) = h2u(c10, c11);
            }
        }
    } else {
        int8_t* D1 = z ? g_k1 : g_q1;
        int8_t* D2 = z ? g_k2 : g_q2;
        float* sOut = z ? g_sk : g_sq;
        const float smul = z ? 1.0f : 0.125f * 1.44269504f;
        const int head = (bn + nw0) >> 6;
        #pragma unroll
        for (int mi = 0; mi < 2; ++mi) {
            const int m0 = bm + mw0 + mi * 16 + erow;
            const float sa0 = sA[m0], sa8 = sA[m0 + 8];
            float v0[16], v1[16];
            #pragma unroll
            for (int ni = 0; ni < 8; ++ni) {
                const int n = bn + nw0 + ni * 8 + ecol;
                const float sb0 = __uint_as_float(sBbits[n])     * (1.f / 127.f);
                const float sb1 = __uint_as_float(sBbits[n + 1]) * (1.f / 127.f);
                const float b0 = bias[n], b1 = bias[n + 1];
                v0[ni * 2 + 0] = ((float)acc.a1[mi][ni][0] + (float)acc.a2[mi][ni][0] * (1.f / 254.f)) * (sa0 * sb0) + b0;
                v0[ni * 2 + 1] = ((float)acc.a1[mi][ni][1] + (float)acc.a2[mi][ni][1] * (1.f / 254.f)) * (sa0 * sb1) + b1;
                v1[ni * 2 + 0] = ((float)acc.a1[mi][ni][2] + (float)acc.a2[mi][ni][2] * (1.f / 254.f)) * (sa8 * sb0) + b0;
                v1[ni * 2 + 1] = ((float)acc.a1[mi][ni][3] + (float)acc.a2[mi][ni][3] * (1.f / 254.f)) * (sa8 * sb1) + b1;
            }
            float mx0 = 0.f, mx1 = 0.f;
            #pragma unroll
            for (int i = 0; i < 16; i++) {
                mx0 = fmaxf(mx0, fabsf(v0[i]));
                mx1 = fmaxf(mx1, fabsf(v1[i]));
            }
            mx0 = fmaxf(mx0, __shfl_xor_sync(0xffffffffu, mx0, 1));
            mx0 = fmaxf(mx0, __shfl_xor_sync(0xffffffffu, mx0, 2));
            mx1 = fmaxf(mx1, __shfl_xor_sync(0xffffffffu, mx1, 1));
            mx1 = fmaxf(mx1, __shfl_xor_sync(0xffffffffu, mx1, 2));
            mx0 = fmaxf(mx0, 1e-20f);
            mx1 = fmaxf(mx1, 1e-20f);
            if ((lane & 3) == 0) {
                sOut[head * S_LEN + m0]     = mx0 * (smul / 127.f);
                sOut[head * S_LEN + m0 + 8] = mx1 * (smul / 127.f);
            }
            const float i0 = 127.f / mx0, i1 = 127.f / mx1;
            #pragma unroll
            for (int ni = 0; ni < 8; ++ni) {
                const int n = bn + nw0 + ni * 8 + ecol;
                uint32_t w2;
                uint32_t w1 = pack_dig(v0[ni * 2] * i0, v0[ni * 2 + 1] * i0, w2);
                *(uint16_t*)(D1 + (size_t)m0 * DMODEL + n) = (uint16_t)w1;
                *(uint16_t*)(D2 + (size_t)m0 * DMODEL + n) = (uint16_t)w2;
                w1 = pack_dig(v1[ni * 2] * i1, v1[ni * 2 + 1] * i1, w2);
                *(uint16_t*)(D1 + (size_t)(m0 + 8) * DMODEL + n) = (uint16_t)w1;
                *(uint16_t*)(D2 + (size_t)(m0 + 8) * DMODEL + n) = (uint16_t)w2;
            }
        }
    }
}

// O projection: fp32 out + bias, 2 CTAs/SM
__global__ __launch_bounds__(256, 2)
void gemm_o_kernel(const float* __restrict__ bias, float* __restrict__ C)
{
    extern __shared__ char sm[];
    const uint32_t sbase = smem_u32(sm);
    const int tid  = threadIdx.x;
    const int lane = tid & 31;
    const int wid  = tid >> 5;
    const int mw0  = (wid & 3) * 32;
    const int nw0  = (wid >> 2) * 64;
    const int bm   = blockIdx.y * 128;
    const int bn   = blockIdx.x * 128;

    GemmAcc acc;
    gemm_mainloop(g_c1 + (size_t)bm * DMODEL, g_c2 + (size_t)bm * DMODEL,
                  g_wo1 + (size_t)bn * DMODEL, g_wo2 + (size_t)bn * DMODEL,
                  sm, sbase, tid, lane, mw0, nw0, acc);

    const unsigned* sBbits = g_wbits + 3 * DMODEL;
    const int erow = lane >> 2;
    const int ecol = (lane & 3) * 2;
    #pragma unroll
    for (int mi = 0; mi < 2; ++mi) {
        const int m0 = bm + mw0 + mi * 16 + erow;
        const float sa0 = g_sc[m0], sa8 = g_sc[m0 + 8];
        #pragma unroll
        for (int ni = 0; ni < 8; ++ni) {
            const int n = bn + nw0 + ni * 8 + ecol;
            const float sb0 = __uint_as_float(sBbits[n])     * (1.f / 127.f);
            const float sb1 = __uint_as_float(sBbits[n + 1]) * (1.f / 127.f);
            const float b0 = bias[n], b1 = bias[n + 1];
            float2 v0, v1;
            v0.x = ((float)acc.a1[mi][ni][0] + (float)acc.a2[mi][ni][0] * (1.f / 254.f)) * (sa0 * sb0) + b0;
            v0.y = ((float)acc.a1[mi][ni][1] + (float)acc.a2[mi][ni][1] * (1.f / 254.f)) * (sa0 * sb1) + b1;
            v1.x = ((float)acc.a1[mi][ni][2] + (float)acc.a2[mi][ni][2] * (1.f / 254.f)) * (sa8 * sb0) + b0;
            v1.y = ((float)acc.a1[mi][ni][3] + (float)acc.a2[mi][ni][3] * (1.f / 254.f)) * (sa8 * sb1) + b1;
            *(float2*)(C + (size_t)m0 * DMODEL + n)       = v0;
            *(float2*)(C + (size_t)(m0 + 8) * DMODEL + n) = v1;
        }
    }
}

// ======================= hybrid flash attention =======================
#define AK_ROWB 80
#define AK_B (128 * AK_ROWB)
#define AV_ROWB 144
#define AV_B (128 * AV_ROWB)
#define ASK_OFF (2 * AK_B + AV_B)
#define ABUF_B (ASK_OFF + 512)
#define ATT_SMEM (2 * ABUF_B)

__global__ __launch_bounds__(256, 2)
void attn_kernel()
{
    extern __shared__ char sm[];
    const uint32_t sbase = smem_u32(sm);

    const int tid  = threadIdx.x;
    const int lane = tid & 31;
    const int w    = tid >> 5;
    const int h    = blockIdx.y;
    const int qt   = (int)gridDim.x - 1 - (int)blockIdx.x;
    const int q0   = qt * 128;
    const int hoff = h * DK;
    const int q0w  = q0 + w * 16;

    const int r  = lane >> 2;
    const int kc = (lane & 3) * 2;

    // Q A-fragments (int8 digits)
    uint32_t q1f[2][4], q2f[2][4];
    {
        const int qb = (lane & 3) * 4;
        #pragma unroll
        for (int g = 0; g < 2; ++g) {
            const size_t bA = (size_t)(q0w + r) * DMODEL + hoff + g * 32 + qb;
            const size_t bB = (size_t)(q0w + r + 8) * DMODEL + hoff + g * 32 + qb;
            q1f[g][0] = *(const uint32_t*)(g_q1 + bA);
            q1f[g][1] = *(const uint32_t*)(g_q1 + bB);
            q1f[g][2] = *(const uint32_t*)(g_q1 + bA + 16);
            q1f[g][3] = *(const uint32_t*)(g_q1 + bB + 16);
            q2f[g][0] = *(const uint32_t*)(g_q2 + bA);
            q2f[g][1] = *(const uint32_t*)(g_q2 + bB);
            q2f[g][2] = *(const uint32_t*)(g_q2 + bA + 16);
            q2f[g][3] = *(const uint32_t*)(g_q2 + bB + 16);
        }
    }
    const float sq0f = g_sq[h * S_LEN + q0w + r]     * (1.f / 254.f);
    const float sq1f = g_sq[h * S_LEN + q0w + r + 8] * (1.f / 254.f);

    auto issue_kv = [&](int kt, int buf) {
        const int k0 = kt * 128;
        const uint32_t sb = sbase + buf * ABUF_B;
        #pragma unroll
        for (int d = 0; d < 2; ++d) {
            const int8_t* src = (d ? g_k2 : g_k1) + (size_t)k0 * DMODEL + hoff;
            #pragma unroll
            for (int j = 0; j < 2; ++j) {
                const int slot = tid + j * 256;
                const int row = slot >> 2, col = slot & 3;
                cp16(sb + d * AK_B + row * AK_ROWB + col * 16,
                     src + (size_t)row * DMODEL + col * 16);
            }
        }
        {
            const __half* src = g_v16 + (size_t)k0 * DMODEL + hoff;
            #pragma unroll
            for (int j = 0; j < 4; ++j) {
                const int slot = tid + j * 256;
                const int row = slot >> 3, col = slot & 7;
                cp16(sb + 2 * AK_B + row * AV_ROWB + col * 16,
                     src + (size_t)row * DMODEL + col * 8);
            }
        }
        if (tid < 32)
            cp16(sb + ASK_OFF + tid * 16, g_sk + h * S_LEN + k0 + tid * 4);
    };

    float m_[2] = { -1e30f, -1e30f }, l_[2] = { 0.f, 0.f };
    float oacc[8][4];
    #pragma unroll
    for (int i = 0; i < 8; i++)
        #pragma unroll
        for (int j = 0; j < 4; j++) oacc[i][j] = 0.f;

    issue_kv(0, 0);
    cp_commit();

    const uint32_t b_off  = (uint32_t)(((lane >> 4) << 3) + (lane & 7));
    const uint32_t kb_off = ((lane >> 3) & 1) * 16;
    const uint32_t vrow   = lane & 15;
    const uint32_t vcol   = (lane >> 4) * 8;

    for (int kt = 0; kt <= qt; ++kt) {
        const int buf = kt & 1;
        const bool hasNext = kt < qt;
        if (hasNext) { issue_kv(kt + 1, buf ^ 1); cp_commit(); }
        if (hasNext) cp_wait1(); else cp_wait0();
        __syncthreads();

        const uint32_t k1b = sbase + buf * ABUF_B;
        const uint32_t k2b = k1b + AK_B;
        const uint32_t v_b = k1b + 2 * AK_B;
        const float* sks = (const float*)(sm + buf * ABUF_B + ASK_OFF);

        #pragma unroll
        for (int half = 0; half < 2; ++half) {
            if (kt == qt && half == 1 && (w * 16 + 15) < 64) break;

            const int kbase = half * 64;

            // ---- S = Q @ K^T over 64 keys (dual-digit int8) ----
            float s[8][4];
            #pragma unroll
            for (int nt2 = 0; nt2 < 4; ++nt2) {
                int a1[2][4] = { {0,0,0,0}, {0,0,0,0} };
                int a2[2][4] = { {0,0,0,0}, {0,0,0,0} };
                #pragma unroll
                for (int g = 0; g < 2; ++g) {
                    const uint32_t addr = (uint32_t)(kbase + nt2 * 16 + b_off) * AK_ROWB + g * 32 + kb_off;
                    uint32_t fb1[4], fb2[4];
                    ldsm_x4(fb1, k1b + addr);
                    ldsm_x4(fb2, k2b + addr);
                    #pragma unroll
                    for (int hf = 0; hf < 2; ++hf) {
                        mma_s8(a1[hf], q1f[g], fb1 + hf * 2);
                        mma_s8(a2[hf], q1f[g], fb2 + hf * 2);
                        mma_s8(a2[hf], q2f[g], fb1 + hf * 2);
                    }
                }
                #pragma unroll
                for (int hf = 0; hf < 2; ++hf) {
                    const float2 sk2 = *(const float2*)(sks + (kbase + (nt2 * 2 + hf) * 8) + kc);
                    s[nt2 * 2 + hf][0] = (float)(a1[hf][0] * 254 + a2[hf][0]) * (sq0f * sk2.x);
                    s[nt2 * 2 + hf][1] = (float)(a1[hf][1] * 254 + a2[hf][1]) * (sq0f * sk2.y);
                    s[nt2 * 2 + hf][2] = (float)(a1[hf][2] * 254 + a2[hf][2]) * (sq1f * sk2.x);
                    s[nt2 * 2 + hf][3] = (float)(a1[hf][3] * 254 + a2[hf][3]) * (sq1f * sk2.y);
                }
            }

            // causal mask on diagonal tile
            if (kt == qt) {
                #pragma unroll
                for (int nt = 0; nt < 8; ++nt) {
                    #pragma unroll
                    for (int c = 0; c < 4; ++c) {
                        const int key = kbase + nt * 8 + kc + (c & 1);
                        const int qq  = w * 16 + r + (c >> 1) * 8;
                        if (key > qq) s[nt][c] = -1e30f;
                    }
                }
            }

            // ---- online softmax (base-2), conditional rescale ----
            float mx0 = -1e30f, mx1 = -1e30f;
            #pragma unroll
            for (int nt = 0; nt < 8; ++nt) {
                mx0 = fmaxf(mx0, fmaxf(s[nt][0], s[nt][1]));
                mx1 = fmaxf(mx1, fmaxf(s[nt][2], s[nt][3]));
            }
            mx0 = fmaxf(mx0, __shfl_xor_sync(0xffffffffu, mx0, 1));
            mx0 = fmaxf(mx0, __shfl_xor_sync(0xffffffffu, mx0, 2));
            mx1 = fmaxf(mx1, __shfl_xor_sync(0xffffffffu, mx1, 1));
            mx1 = fmaxf(mx1, __shfl_xor_sync(0xffffffffu, mx1, 2));

            const bool upd = (mx0 > m_[0]) || (mx1 > m_[1]);
            if (__any_sync(0xffffffffu, upd)) {
                const float nm0 = fmaxf(m_[0], mx0), nm1 = fmaxf(m_[1], mx1);
                const float al0 = ex2f(m_[0] - nm0), al1 = ex2f(m_[1] - nm1);
                l_[0] *= al0;  l_[1] *= al1;
                m_[0] = nm0;   m_[1] = nm1;
                #pragma unroll
                for (int dt = 0; dt < 8; ++dt) {
                    oacc[dt][0] *= al0; oacc[dt][1] *= al0;
                    oacc[dt][2] *= al1; oacc[dt][3] *= al1;
                }
            }

            float rs0 = 0.f, rs1 = 0.f;
            #pragma unroll
            for (int nt = 0; nt < 8; ++nt) {
                s[nt][0] = ex2f(s[nt][0] - m_[0]);
                s[nt][1] = ex2f(s[nt][1] - m_[0]);
                s[nt][2] = ex2f(s[nt][2] - m_[1]);
                s[nt][3] = ex2f(s[nt][3] - m_[1]);
                rs0 += s[nt][0] + s[nt][1];
                rs1 += s[nt][2] + s[nt][3];
            }
            rs0 += __shfl_xor_sync(0xffffffffu, rs0, 1);
            rs0 += __shfl_xor_sync(0xffffffffu, rs0, 2);
            rs1 += __shfl_xor_sync(0xffffffffu, rs1, 1);
            rs1 += __shfl_xor_sync(0xffffffffu, rs1, 2);
            l_[0] += rs0;
            l_[1] += rs1;

            // ---- O += P @ V over 64 keys ----
            #pragma unroll
            for (int j = 0; j < 4; ++j) {
                uint32_t pa[4];
                pa[0] = h2u(s[2*j][0],   s[2*j][1]);
                pa[1] = h2u(s[2*j][2],   s[2*j][3]);
                pa[2] = h2u(s[2*j+1][0], s[2*j+1][1]);
                pa[3] = h2u(s[2*j+1][2], s[2*j+1][3]);

                const uint32_t abase = (kbase + j * 16 + vrow) * AV_ROWB + vcol * 2;
                #pragma unroll
                for (int dg = 0; dg < 4; ++dg) {
                    uint32_t bv[4];
                    ldsm_x4_t(bv, v_b + abase + dg * 32);
                    mma_f16(oacc[dg * 2 + 0], pa, bv + 0);
                    mma_f16(oacc[dg * 2 + 1], pa, bv + 2);
                }
            }
        }
        __syncthreads();
    }

    // epilogue: normalize, write fp32 ctx
    const float inv0 = 1.f / l_[0], inv1 = 1.f / l_[1];
    #pragma unroll
    for (int dt = 0; dt < 8; ++dt) {
        const size_t d = (size_t)hoff + dt * 8 + kc;
        const size_t rowA = (size_t)(q0w + r) * DMODEL + d;
        const size_t rowB = (size_t)(q0w + r + 8) * DMODEL + d;
        float2 a0 = { oacc[dt][0] * inv0, oacc[dt][1] * inv0 };
        float2 a1 = { oacc[dt][2] * inv1, oacc[dt][3] * inv1 };
        *(float2*)(g_ctx + rowA) = a0;
        *(float2*)(g_ctx + rowB) = a1;
    }
}

// ======================= host launcher =======================
extern "C" void kernel_launch(void* const* d_in, const int* in_sizes, int n_in,
                              void* d_out, int out_size)
{
    (void)in_sizes; (void)n_in; (void)out_size;
    const float* x  = (const float*)d_in[0];
    const float* Wq = (const float*)d_in[2];
    const float* bq = (const float*)d_in[3];
    const float* Wk = (const float*)d_in[4];
    const float* bk = (const float*)d_in[5];
    const float* Wv = (const float*)d_in[6];
    const float* bv = (const float*)d_in[7];
    const float* Wo = (const float*)d_in[8];
    const float* bo = (const float*)d_in[9];
    float* out = (float*)d_out;

    int8_t *x1, *x2, *c1, *c2;
    float *sx, *sc, *ctx;
    cudaGetSymbolAddress((void**)&x1, g_x1);
    cudaGetSymbolAddress((void**)&x2, g_x2);
    cudaGetSymbolAddress((void**)&sx, g_sx);
    cudaGetSymbolAddress((void**)&c1, g_c1);
    cudaGetSymbolAddress((void**)&c2, g_c2);
    cudaGetSymbolAddress((void**)&sc, g_sc);
    cudaGetSymbolAddress((void**)&ctx, g_ctx);

    cudaFuncSetAttribute(gemm_qkv_kernel,
                         cudaFuncAttributeMaxDynamicSharedMemorySize, QGEMM_SMEM);
    cudaFuncSetAttribute(gemm_o_kernel,
                         cudaFuncAttributeMaxDynamicSharedMemorySize, QGEMM_SMEM);
    cudaFuncSetAttribute(attn_kernel,
                         cudaFuncAttributeMaxDynamicSharedMemorySize, ATT_SMEM);

    // 1: weight column max (parallel, no atomics)
    colmax4_kernel<<<dim3(8, 4), 1024>>>(Wq, Wk, Wv, Wo);
    // 2: weight transpose + quant
    transpose_quant4_kernel<<<dim3(32, 32, 4), 256>>>(Wq, Wk, Wv, Wo);
    // 3: input row-quant
    rowquant_kernel<<<S_LEN, 256>>>(x, x1, x2, sx);
    // 4: fused Q/K/V projections  (profiled slot)
    gemm_qkv_kernel<<<dim3(8, 32, 3), 256, QGEMM_SMEM>>>(bq, bk, bv);
    // 5: attention
    attn_kernel<<<dim3(S_LEN / 128, NHEADS), 256, ATT_SMEM>>>();
    // 6: ctx row-quant
    rowquant_kernel<<<S_LEN, 256>>>(ctx, c1, c2, sc);
    // 7: O projection
    gemm_o_kernel<<<dim3(8, 32), 256, QGEMM_SMEM>>>(bo, out);
}

// round 14
// speedup vs baseline: 1.2999x; 1.2999x over previous
#include <cuda_runtime.h>
#include <cuda_bf16.h>
#include <cuda_fp16.h>
#include <cstdint>
#include <math.h>

#define S_LEN  4096
#define DMODEL 1024
#define NHEADS 16
#define DK     64

// ======================= scratch (device globals) =======================
__device__ int8_t g_x1[(size_t)S_LEN * DMODEL];
__device__ int8_t g_x2[(size_t)S_LEN * DMODEL];
__device__ float  g_sx[S_LEN];

__device__ int8_t g_wq1[(size_t)DMODEL * DMODEL];
__device__ int8_t g_wq2[(size_t)DMODEL * DMODEL];
__device__ int8_t g_wk1[(size_t)DMODEL * DMODEL];
__device__ int8_t g_wk2[(size_t)DMODEL * DMODEL];
__device__ int8_t g_wv1[(size_t)DMODEL * DMODEL];
__device__ int8_t g_wv2[(size_t)DMODEL * DMODEL];
__device__ int8_t g_wo1[(size_t)DMODEL * DMODEL];
__device__ int8_t g_wo2[(size_t)DMODEL * DMODEL];
__device__ unsigned g_wbits[4 * DMODEL];

// attention operands
__device__ int8_t g_q1[(size_t)S_LEN * DMODEL];
__device__ int8_t g_q2[(size_t)S_LEN * DMODEL];
__device__ int8_t g_k1[(size_t)S_LEN * DMODEL];
__device__ int8_t g_k2[(size_t)S_LEN * DMODEL];
__device__ float  g_sq[NHEADS * S_LEN];
__device__ float  g_sk[NHEADS * S_LEN];
__device__ __half g_v16[(size_t)S_LEN * DMODEL];

__device__ float  g_ctx[(size_t)S_LEN * DMODEL];
__device__ int8_t g_c1[(size_t)S_LEN * DMODEL];
__device__ int8_t g_c2[(size_t)S_LEN * DMODEL];
__device__ float  g_sc[S_LEN];

// ======================= helpers =======================
__device__ __forceinline__ uint32_t smem_u32(const void* p) {
    uint32_t a;
    asm("{ .reg .u64 t; cvta.to.shared.u64 t, %1; cvt.u32.u64 %0, t; }" : "=r"(a) : "l"(p));
    return a;
}
__device__ __forceinline__ void cp16(uint32_t saddr, const void* g) {
    asm volatile("cp.async.ca.shared.global [%0], [%1], 16;" :: "r"(saddr), "l"(g));
}
__device__ __forceinline__ void cp_commit() { asm volatile("cp.async.commit_group;"); }
__device__ __forceinline__ void cp_wait1()  { asm volatile("cp.async.wait_group 1;"); }
__device__ __forceinline__ void cp_wait0()  { asm volatile("cp.async.wait_group 0;"); }

__device__ __forceinline__ void ldsm_x4(uint32_t* r, uint32_t addr) {
    asm volatile("ldmatrix.sync.aligned.m8n8.x4.shared.b16 {%0,%1,%2,%3}, [%4];"
                 : "=r"(r[0]), "=r"(r[1]), "=r"(r[2]), "=r"(r[3]) : "r"(addr));
}
__device__ __forceinline__ void ldsm_x4_t(uint32_t* r, uint32_t addr) {
    asm volatile("ldmatrix.sync.aligned.m8n8.x4.trans.shared.b16 {%0,%1,%2,%3}, [%4];"
                 : "=r"(r[0]), "=r"(r[1]), "=r"(r[2]), "=r"(r[3]) : "r"(addr));
}
__device__ __forceinline__ void mma_s8(int* c, const uint32_t* a, const uint32_t* b) {
    asm volatile(
        "mma.sync.aligned.m16n8k32.row.col.s32.s8.s8.s32 "
        "{%0,%1,%2,%3}, {%4,%5,%6,%7}, {%8,%9}, {%0,%1,%2,%3};"
        : "+r"(c[0]), "+r"(c[1]), "+r"(c[2]), "+r"(c[3])
        : "r"(a[0]), "r"(a[1]), "r"(a[2]), "r"(a[3]), "r"(b[0]), "r"(b[1]));
}
__device__ __forceinline__ void mma_f16(float* c, const uint32_t* a, const uint32_t* b) {
    asm volatile(
        "mma.sync.aligned.m16n8k16.row.col.f32.f16.f16.f32 "
        "{%0,%1,%2,%3}, {%4,%5,%6,%7}, {%8,%9}, {%0,%1,%2,%3};"
        : "+f"(c[0]), "+f"(c[1]), "+f"(c[2]), "+f"(c[3])
        : "r"(a[0]), "r"(a[1]), "r"(a[2]), "r"(a[3]), "r"(b[0]), "r"(b[1]));
}
__device__ __forceinline__ float ex2f(float x) {
    float y;
    asm("ex2.approx.f32 %0, %1;" : "=f"(y) : "f"(x));
    return y;
}
__device__ __forceinline__ uint32_t h2u(float x, float y) {
    __half2 h = __floats2half2_rn(x, y);
    return *(uint32_t*)&h;
}
__device__ __forceinline__ void digits2(float alpha, int& d1, int& d2) {
    d1 = __float2int_rn(alpha);
    d2 = __float2int_rn((alpha - (float)d1) * 254.f);
}
__device__ __forceinline__ uint32_t pack_dig(float a, float b, uint32_t& w2) {
    int a1, a2, b1, b2;
    digits2(a, a1, a2);
    digits2(b, b1, b2);
    w2 = (uint32_t)(a2 & 0xff) | (((uint32_t)(b2 & 0xff)) << 8);
    return (uint32_t)(a1 & 0xff) | (((uint32_t)(b1 & 0xff)) << 8);
}
__device__ __forceinline__ uint32_t pack4b(int a, int b, int c, int d) {
    return (uint32_t)(a & 0xff) | (((uint32_t)(b & 0xff)) << 8) |
           (((uint32_t)(c & 0xff)) << 16) | (((uint32_t)(d & 0xff)) << 24);
}

// ======================= weight prep =======================
__global__ __launch_bounds__(1024)
void colmax4_kernel(const float* __restrict__ Wq, const float* __restrict__ Wk,
                    const float* __restrict__ Wv, const float* __restrict__ Wo)
{
    const int z = blockIdx.y;
    const float* W = (z == 0) ? Wq : (z == 1) ? Wk : (z == 2) ? Wv : Wo;
    unsigned* bits = g_wbits + z * DMODEL;

    const int tid  = threadIdx.x;
    const int col  = blockIdx.x * 128 + (tid & 127);
    const int part = tid >> 7;

    float m = 0.f;
    #pragma unroll 8
    for (int r = part; r < DMODEL; r += 8)
        m = fmaxf(m, fabsf(W[(size_t)r * DMODEL + col]));

    __shared__ float red[8][128];
    red[part][tid & 127] = m;
    __syncthreads();
    if (tid < 128) {
        float mm = red[0][tid];
        #pragma unroll
        for (int i = 1; i < 8; ++i) mm = fmaxf(mm, red[i][tid]);
        bits[blockIdx.x * 128 + tid] = __float_as_uint(fmaxf(mm, 1e-30f));
    }
}

__global__ __launch_bounds__(256)
void transpose_quant4_kernel(const float* __restrict__ W0, const float* __restrict__ W1,
                             const float* __restrict__ W2, const float* __restrict__ W3)
{
    const int z = blockIdx.z;
    const float* W = (z == 0) ? W0 : (z == 1) ? W1 : (z == 2) ? W2 : W3;
    int8_t* B1 = (z == 0) ? g_wq1 : (z == 1) ? g_wk1 : (z == 2) ? g_wv1 : g_wo1;
    int8_t* B2 = (z == 0) ? g_wq2 : (z == 1) ? g_wk2 : (z == 2) ? g_wv2 : g_wo2;
    const unsigned* b = g_wbits + z * DMODEL;

    __shared__ float t[32][33];
    const int n0 = blockIdx.x * 32, k0 = blockIdx.y * 32;
    const int lx = threadIdx.x & 31, ly = threadIdx.x >> 5;
    #pragma unroll
    for (int i = 0; i < 32; i += 8)
        t[ly + i][lx] = W[(size_t)(k0 + ly + i) * DMODEL + n0 + lx];
    __syncthreads();
    #pragma unroll
    for (int i = 0; i < 32; i += 8) {
        const int n = n0 + ly + i;
        const float inv = 127.f / __uint_as_float(b[n]);
        int d1, d2;
        digits2(t[lx][ly + i] * inv, d1, d2);
        const size_t o = (size_t)n * DMODEL + k0 + lx;
        B1[o] = (int8_t)d1;
        B2[o] = (int8_t)d2;
    }
}

__global__ __launch_bounds__(256)
void rowquant_kernel(const float* __restrict__ src,
                     int8_t* __restrict__ D1, int8_t* __restrict__ D2,
                     float* __restrict__ s)
{
    const int row = blockIdx.x;
    const int tid = threadIdx.x;
    const float4 v = ((const float4*)(src + (size_t)row * DMODEL))[tid];
    float m = fmaxf(fmaxf(fabsf(v.x), fabsf(v.y)), fmaxf(fabsf(v.z), fabsf(v.w)));
    #pragma unroll
    for (int o = 16; o >= 1; o >>= 1)
        m = fmaxf(m, __shfl_xor_sync(0xffffffffu, m, o));
    __shared__ float red[8];
    if ((tid & 31) == 0) red[tid >> 5] = m;
    __syncthreads();
    float mm = red[0];
    #pragma unroll
    for (int i = 1; i < 8; i++) mm = fmaxf(mm, red[i]);
    mm = fmaxf(mm, 1e-30f);
    if (tid == 0) s[row] = mm * (1.f / 127.f);
    const float inv = 127.f / mm;
    int d1, d2;
    char4 c1, c2;
    digits2(v.x * inv, d1, d2); c1.x = (char)d1; c2.x = (char)d2;
    digits2(v.y * inv, d1, d2); c1.y = (char)d1; c2.y = (char)d2;
    digits2(v.z * inv, d1, d2); c1.z = (char)d1; c2.z = (char)d2;
    digits2(v.w * inv, d1, d2); c1.w = (char)d1; c2.w = (char)d2;
    ((char4*)(D1 + (size_t)row * DMODEL))[tid] = c1;
    ((char4*)(D2 + (size_t)row * DMODEL))[tid] = c2;
}

// ======================= int8 dual-digit GEMM, 128x64 tile =======================
// 8 warps, each owns 16 rows x 64 cols. acc = 64 int regs -> 2 CTAs/SM.
#define QBK 64
#define QNCH (DMODEL / QBK)
#define QROWB 80
#define QARR_A (128 * QROWB)             // 10240 per A digit
#define QARR_B2 (64 * QROWB)             // 5120 per B digit
#define QBOFF (2 * QARR_A)               // B arrays after both A digits
#define QSTAGE_B (2 * QARR_A + 2 * QARR_B2)   // 30720
#define QGEMM_SMEM (2 * QSTAGE_B)        // 61440

struct GemmAcc { int a1[8][4]; int a2[8][4]; };

__device__ __forceinline__ void gemm_mainloop64(
    const int8_t* A1p, const int8_t* A2p, const int8_t* B1p, const int8_t* B2p,
    uint32_t sbase, int tid, int lane, int mw0, GemmAcc& acc)
{
    #pragma unroll
    for (int j = 0; j < 8; j++)
        #pragma unroll
        for (int q = 0; q < 4; q++) { acc.a1[j][q] = 0; acc.a2[j][q] = 0; }

    const int a_row = lane & 15;
    const int a_kb  = (lane >> 4) * 16;
    const int b_row = ((lane >> 4) << 3) + (lane & 7);
    const int b_kb  = ((lane >> 3) & 1) * 16;

    auto issue_loads = [&](int c, int stage) {
        const int k0 = c * QBK;
        const uint32_t sb = sbase + stage * QSTAGE_B;
        // A digits: 512 slots of 16B each, 2 per thread
        #pragma unroll
        for (int jj = 0; jj < 2; jj++) {
            const int slot = tid + jj * 256;
            const int row = slot >> 2, col = slot & 3;
            cp16(sb + 0 * QARR_A + row * QROWB + col * 16,
                 A1p + (size_t)row * DMODEL + k0 + col * 16);
            cp16(sb + 1 * QARR_A + row * QROWB + col * 16,
                 A2p + (size_t)row * DMODEL + k0 + col * 16);
        }
        // B digits: 256 slots each, 1 per thread
        {
            const int row = tid >> 2, col = tid & 3;
            cp16(sb + QBOFF + 0 * QARR_B2 + row * QROWB + col * 16,
                 B1p + (size_t)row * DMODEL + k0 + col * 16);
            cp16(sb + QBOFF + 1 * QARR_B2 + row * QROWB + col * 16,
                 B2p + (size_t)row * DMODEL + k0 + col * 16);
        }
    };

    issue_loads(0, 0);
    cp_commit();

    for (int c = 0; c < QNCH; ++c) {
        const int stage = c & 1;
        const bool hasNext = (c + 1 < QNCH);
        if (hasNext) { issue_loads(c + 1, stage ^ 1); cp_commit(); }
        if (hasNext) cp_wait1(); else cp_wait0();
        __syncthreads();

        const uint32_t sb = sbase + stage * QSTAGE_B;
        #pragma unroll
        for (int ks = 0; ks < 2; ++ks) {
            const int kb = ks * 32;
            uint32_t fa1[4], fa2[4];
            const uint32_t aoff = (uint32_t)(mw0 + a_row) * QROWB + kb + a_kb;
            ldsm_x4(fa1, sb + 0 * QARR_A + aoff);
            ldsm_x4(fa2, sb + 1 * QARR_A + aoff);
            #pragma unroll
            for (int nt2 = 0; nt2 < 4; ++nt2) {
                const uint32_t boff = QBOFF + (uint32_t)(nt2 * 16 + b_row) * QROWB + kb + b_kb;
                uint32_t fb1[4], fb2[4];
                ldsm_x4(fb1, sb + 0 * QARR_B2 + boff);
                ldsm_x4(fb2, sb + 1 * QARR_B2 + boff);
                #pragma unroll
                for (int half = 0; half < 2; ++half) {
                    mma_s8(acc.a1[nt2 * 2 + half], fa1, fb1 + half * 2);
                    mma_s8(acc.a2[nt2 * 2 + half], fa1, fb2 + half * 2);
                    mma_s8(acc.a2[nt2 * 2 + half], fa2, fb1 + half * 2);
                }
            }
        }
        __syncthreads();
    }
}

// fused Q/K/V projection: grid (16, 32, 3), 2 CTAs/SM
__global__ __launch_bounds__(256, 2)
void gemm_qkv_kernel(const float* __restrict__ bq,
                     const float* __restrict__ bk,
                     const float* __restrict__ bv)
{
    extern __shared__ char sm[];
    const uint32_t sbase = smem_u32(sm);
    const int tid  = threadIdx.x;
    const int lane = tid & 31;
    const int wid  = tid >> 5;
    const int mw0  = wid * 16;
    const int bm   = blockIdx.y * 128;
    const int bn   = blockIdx.x * 64;
    const int z    = blockIdx.z;

    const int8_t* B1 = (z == 0) ? g_wq1 : (z == 1) ? g_wk1 : g_wv1;
    const int8_t* B2 = (z == 0) ? g_wq2 : (z == 1) ? g_wk2 : g_wv2;
    const float* bias = (z == 0) ? bq : (z == 1) ? bk : bv;
    const unsigned* sBbits = g_wbits + z * DMODEL;

    GemmAcc acc;
    gemm_mainloop64(g_x1 + (size_t)bm * DMODEL, g_x2 + (size_t)bm * DMODEL,
                    B1 + (size_t)bn * DMODEL, B2 + (size_t)bn * DMODEL,
                    sbase, tid, lane, mw0, acc);

    const int erow = lane >> 2;
    const int ecol = (lane & 3) * 2;
    const float* sA = g_sx;
    const int m0 = bm + mw0 + erow;
    const float sa0 = sA[m0], sa8 = sA[m0 + 8];

    if (z == 2) {
        #pragma unroll
        for (int ni = 0; ni < 8; ++ni) {
            const int n = bn + ni * 8 + ecol;
            const float sb0 = __uint_as_float(sBbits[n])     * (1.f / 127.f);
            const float sb1 = __uint_as_float(sBbits[n + 1]) * (1.f / 127.f);
            const float b0 = bias[n], b1 = bias[n + 1];
            const float c00 = ((float)acc.a1[ni][0] + (float)acc.a2[ni][0] * (1.f / 254.f)) * (sa0 * sb0) + b0;
            const float c01 = ((float)acc.a1[ni][1] + (float)acc.a2[ni][1] * (1.f / 254.f)) * (sa0 * sb1) + b1;
            const float c10 = ((float)acc.a1[ni][2] + (float)acc.a2[ni][2] * (1.f / 254.f)) * (sa8 * sb0) + b0;
            const float c11 = ((float)acc.a1[ni][3] + (float)acc.a2[ni][3] * (1.f / 254.f)) * (sa8 * sb1) + b1;
            *(uint32_t*)(g_v16 + (size_t)m0 * DMODEL + n)       = h2u(c00, c01);
            *(uint32_t*)(g_v16 + (size_t)(m0 + 8) * DMODEL + n) = h2u(c10, c11);
        }
    } else {
        int8_t* D1 = z ? g_k1 : g_q1;
        int8_t* D2 = z ? g_k2 : g_q2;
        float* sOut = z ? g_sk : g_sq;
        const float smul = z ? 1.0f : 0.125f * 1.44269504f;
        const int head = bn >> 6;
        float v0[16], v1[16];
        #pragma unroll
        for (int ni = 0; ni < 8; ++ni) {
            const int n = bn + ni * 8 + ecol;
            const float sb0 = __uint_as_float(sBbits[n])     * (1.f / 127.f);
            const float sb1 = __uint_as_float(sBbits[n + 1]) * (1.f / 127.f);
            const float b0 = bias[n], b1 = bias[n + 1];
            v0[ni * 2 + 0] = ((float)acc.a1[ni][0] + (float)acc.a2[ni][0] * (1.f / 254.f)) * (sa0 * sb0) + b0;
            v0[ni * 2 + 1] = ((float)acc.a1[ni][1] + (float)acc.a2[ni][1] * (1.f / 254.f)) * (sa0 * sb1) + b1;
            v1[ni * 2 + 0] = ((float)acc.a1[ni][2] + (float)acc.a2[ni][2] * (1.f / 254.f)) * (sa8 * sb0) + b0;
            v1[ni * 2 + 1] = ((float)acc.a1[ni][3] + (float)acc.a2[ni][3] * (1.f / 254.f)) * (sa8 * sb1) + b1;
        }
        float mx0 = 0.f, mx1 = 0.f;
        #pragma unroll
        for (int i = 0; i < 16; i++) {
            mx0 = fmaxf(mx0, fabsf(v0[i]));
            mx1 = fmaxf(mx1, fabsf(v1[i]));
        }
        mx0 = fmaxf(mx0, __shfl_xor_sync(0xffffffffu, mx0, 1));
        mx0 = fmaxf(mx0, __shfl_xor_sync(0xffffffffu, mx0, 2));
        mx1 = fmaxf(mx1, __shfl_xor_sync(0xffffffffu, mx1, 1));
        mx1 = fmaxf(mx1, __shfl_xor_sync(0xffffffffu, mx1, 2));
        mx0 = fmaxf(mx0, 1e-20f);
        mx1 = fmaxf(mx1, 1e-20f);
        if ((lane & 3) == 0) {
            sOut[head * S_LEN + m0]     = mx0 * (smul / 127.f);
            sOut[head * S_LEN + m0 + 8] = mx1 * (smul / 127.f);
        }
        const float i0 = 127.f / mx0, i1 = 127.f / mx1;
        #pragma unroll
        for (int ni = 0; ni < 8; ++ni) {
            const int n = bn + ni * 8 + ecol;
            uint32_t w2;
            uint32_t w1 = pack_dig(v0[ni * 2] * i0, v0[ni * 2 + 1] * i0, w2);
            *(uint16_t*)(D1 + (size_t)m0 * DMODEL + n) = (uint16_t)w1;
            *(uint16_t*)(D2 + (size_t)m0 * DMODEL + n) = (uint16_t)w2;
            w1 = pack_dig(v1[ni * 2] * i1, v1[ni * 2 + 1] * i1, w2);
            *(uint16_t*)(D1 + (size_t)(m0 + 8) * DMODEL + n) = (uint16_t)w1;
            *(uint16_t*)(D2 + (size_t)(m0 + 8) * DMODEL + n) = (uint16_t)w2;
        }
    }
}

// O projection: fp32 out + bias, grid (16, 32), 2 CTAs/SM
__global__ __launch_bounds__(256, 2)
void gemm_o_kernel(const float* __restrict__ bias, float* __restrict__ C)
{
    extern __shared__ char sm[];
    const uint32_t sbase = smem_u32(sm);
    const int tid  = threadIdx.x;
    const int lane = tid & 31;
    const int wid  = tid >> 5;
    const int mw0  = wid * 16;
    const int bm   = blockIdx.y * 128;
    const int bn   = blockIdx.x * 64;

    GemmAcc acc;
    gemm_mainloop64(g_c1 + (size_t)bm * DMODEL, g_c2 + (size_t)bm * DMODEL,
                    g_wo1 + (size_t)bn * DMODEL, g_wo2 + (size_t)bn * DMODEL,
                    sbase, tid, lane, mw0, acc);

    const unsigned* sBbits = g_wbits + 3 * DMODEL;
    const int erow = lane >> 2;
    const int ecol = (lane & 3) * 2;
    const int m0 = bm + mw0 + erow;
    const float sa0 = g_sc[m0], sa8 = g_sc[m0 + 8];
    #pragma unroll
    for (int ni = 0; ni < 8; ++ni) {
        const int n = bn + ni * 8 + ecol;
        const float sb0 = __uint_as_float(sBbits[n])     * (1.f / 127.f);
        const float sb1 = __uint_as_float(sBbits[n + 1]) * (1.f / 127.f);
        const float b0 = bias[n], b1 = bias[n + 1];
        float2 v0, v1;
        v0.x = ((float)acc.a1[ni][0] + (float)acc.a2[ni][0] * (1.f / 254.f)) * (sa0 * sb0) + b0;
        v0.y = ((float)acc.a1[ni][1] + (float)acc.a2[ni][1] * (1.f / 254.f)) * (sa0 * sb1) + b1;
        v1.x = ((float)acc.a1[ni][2] + (float)acc.a2[ni][2] * (1.f / 254.f)) * (sa8 * sb0) + b0;
        v1.y = ((float)acc.a1[ni][3] + (float)acc.a2[ni][3] * (1.f / 254.f)) * (sa8 * sb1) + b1;
        *(float2*)(C + (size_t)m0 * DMODEL + n)       = v0;
        *(float2*)(C + (size_t)(m0 + 8) * DMODEL + n) = v1;
    }
}

// ======================= hybrid flash attention (unchanged from R11) =======================
#define AK_ROWB 80
#define AK_B (128 * AK_ROWB)
#define AV_ROWB 144
#define AV_B (128 * AV_ROWB)
#define ASK_OFF (2 * AK_B + AV_B)
#define ABUF_B (ASK_OFF + 512)
#define ATT_SMEM (2 * ABUF_B)

__global__ __launch_bounds__(256, 2)
void attn_kernel()
{
    extern __shared__ char sm[];
    const uint32_t sbase = smem_u32(sm);

    const int tid  = threadIdx.x;
    const int lane = tid & 31;
    const int w    = tid >> 5;
    const int h    = blockIdx.y;
    const int qt   = (int)gridDim.x - 1 - (int)blockIdx.x;
    const int q0   = qt * 128;
    const int hoff = h * DK;
    const int q0w  = q0 + w * 16;

    const int r  = lane >> 2;
    const int kc = (lane & 3) * 2;

    uint32_t q1f[2][4], q2f[2][4];
    {
        const int qb = (lane & 3) * 4;
        #pragma unroll
        for (int g = 0; g < 2; ++g) {
            const size_t bA = (size_t)(q0w + r) * DMODEL + hoff + g * 32 + qb;
            const size_t bB = (size_t)(q0w + r + 8) * DMODEL + hoff + g * 32 + qb;
            q1f[g][0] = *(const uint32_t*)(g_q1 + bA);
            q1f[g][1] = *(const uint32_t*)(g_q1 + bB);
            q1f[g][2] = *(const uint32_t*)(g_q1 + bA + 16);
            q1f[g][3] = *(const uint32_t*)(g_q1 + bB + 16);
            q2f[g][0] = *(const uint32_t*)(g_q2 + bA);
            q2f[g][1] = *(const uint32_t*)(g_q2 + bB);
            q2f[g][2] = *(const uint32_t*)(g_q2 + bA + 16);
            q2f[g][3] = *(const uint32_t*)(g_q2 + bB + 16);
        }
    }
    const float sq0f = g_sq[h * S_LEN + q0w + r]     * (1.f / 254.f);
    const float sq1f = g_sq[h * S_LEN + q0w + r + 8] * (1.f / 254.f);

    auto issue_kv = [&](int kt, int buf) {
        const int k0 = kt * 128;
        const uint32_t sb = sbase + buf * ABUF_B;
        #pragma unroll
        for (int d = 0; d < 2; ++d) {
            const int8_t* src = (d ? g_k2 : g_k1) + (size_t)k0 * DMODEL + hoff;
            #pragma unroll
            for (int j = 0; j < 2; ++j) {
                const int slot = tid + j * 256;
                const int row = slot >> 2, col = slot & 3;
                cp16(sb + d * AK_B + row * AK_ROWB + col * 16,
                     src + (size_t)row * DMODEL + col * 16);
            }
        }
        {
            const __half* src = g_v16 + (size_t)k0 * DMODEL + hoff;
            #pragma unroll
            for (int j = 0; j < 4; ++j) {
                const int slot = tid + j * 256;
                const int row = slot >> 3, col = slot & 7;
                cp16(sb + 2 * AK_B + row * AV_ROWB + col * 16,
                     src + (size_t)row * DMODEL + col * 8);
            }
        }
        if (tid < 32)
            cp16(sb + ASK_OFF + tid * 16, g_sk + h * S_LEN + k0 + tid * 4);
    };

    float m_[2] = { -1e30f, -1e30f }, l_[2] = { 0.f, 0.f };
    float oacc[8][4];
    #pragma unroll
    for (int i = 0; i < 8; i++)
        #pragma unroll
        for (int j = 0; j < 4; j++) oacc[i][j] = 0.f;

    issue_kv(0, 0);
    cp_commit();

    const uint32_t b_off  = (uint32_t)(((lane >> 4) << 3) + (lane & 7));
    const uint32_t kb_off = ((lane >> 3) & 1) * 16;
    const uint32_t vrow   = lane & 15;
    const uint32_t vcol   = (lane >> 4) * 8;

    for (int kt = 0; kt <= qt; ++kt) {
        const int buf = kt & 1;
        const bool hasNext = kt < qt;
        if (hasNext) { issue_kv(kt + 1, buf ^ 1); cp_commit(); }
        if (hasNext) cp_wait1(); else cp_wait0();
        __syncthreads();

        const uint32_t k1b = sbase + buf * ABUF_B;
        const uint32_t k2b = k1b + AK_B;
        const uint32_t v_b = k1b + 2 * AK_B;
        const float* sks = (const float*)(sm + buf * ABUF_B + ASK_OFF);

        #pragma unroll
        for (int half = 0; half < 2; ++half) {
            if (kt == qt && half == 1 && (w * 16 + 15) < 64) break;

            const int kbase = half * 64;

            float s[8][4];
            #pragma unroll
            for (int nt2 = 0; nt2 < 4; ++nt2) {
                int a1[2][4] = { {0,0,0,0}, {0,0,0,0} };
                int a2[2][4] = { {0,0,0,0}, {0,0,0,0} };
                #pragma unroll
                for (int g = 0; g < 2; ++g) {
                    const uint32_t addr = (uint32_t)(kbase + nt2 * 16 + b_off) * AK_ROWB + g * 32 + kb_off;
                    uint32_t fb1[4], fb2[4];
                    ldsm_x4(fb1, k1b + addr);
                    ldsm_x4(fb2, k2b + addr);
                    #pragma unroll
                    for (int hf = 0; hf < 2; ++hf) {
                        mma_s8(a1[hf], q1f[g], fb1 + hf * 2);
                        mma_s8(a2[hf], q1f[g], fb2 + hf * 2);
                        mma_s8(a2[hf], q2f[g], fb1 + hf * 2);
                    }
                }
                #pragma unroll
                for (int hf = 0; hf < 2; ++hf) {
                    const float2 sk2 = *(const float2*)(sks + (kbase + (nt2 * 2 + hf) * 8) + kc);
                    s[nt2 * 2 + hf][0] = (float)(a1[hf][0] * 254 + a2[hf][0]) * (sq0f * sk2.x);
                    s[nt2 * 2 + hf][1] = (float)(a1[hf][1] * 254 + a2[hf][1]) * (sq0f * sk2.y);
                    s[nt2 * 2 + hf][2] = (float)(a1[hf][2] * 254 + a2[hf][2]) * (sq1f * sk2.x);
                    s[nt2 * 2 + hf][3] = (float)(a1[hf][3] * 254 + a2[hf][3]) * (sq1f * sk2.y);
                }
            }

            if (kt == qt) {
                #pragma unroll
                for (int nt = 0; nt < 8; ++nt) {
                    #pragma unroll
                    for (int c = 0; c < 4; ++c) {
                        const int key = kbase + nt * 8 + kc + (c & 1);
                        const int qq  = w * 16 + r + (c >> 1) * 8;
                        if (key > qq) s[nt][c] = -1e30f;
                    }
                }
            }

            float mx0 = -1e30f, mx1 = -1e30f;
            #pragma unroll
            for (int nt = 0; nt < 8; ++nt) {
                mx0 = fmaxf(mx0, fmaxf(s[nt][0], s[nt][1]));
                mx1 = fmaxf(mx1, fmaxf(s[nt][2], s[nt][3]));
            }
            mx0 = fmaxf(mx0, __shfl_xor_sync(0xffffffffu, mx0, 1));
            mx0 = fmaxf(mx0, __shfl_xor_sync(0xffffffffu, mx0, 2));
            mx1 = fmaxf(mx1, __shfl_xor_sync(0xffffffffu, mx1, 1));
            mx1 = fmaxf(mx1, __shfl_xor_sync(0xffffffffu, mx1, 2));

            const bool upd = (mx0 > m_[0]) || (mx1 > m_[1]);
            if (__any_sync(0xffffffffu, upd)) {
                const float nm0 = fmaxf(m_[0], mx0), nm1 = fmaxf(m_[1], mx1);
                const float al0 = ex2f(m_[0] - nm0), al1 = ex2f(m_[1] - nm1);
                l_[0] *= al0;  l_[1] *= al1;
                m_[0] = nm0;   m_[1] = nm1;
                #pragma unroll
                for (int dt = 0; dt < 8; ++dt) {
                    oacc[dt][0] *= al0; oacc[dt][1] *= al0;
                    oacc[dt][2] *= al1; oacc[dt][3] *= al1;
                }
            }

            float rs0 = 0.f, rs1 = 0.f;
            #pragma unroll
            for (int nt = 0; nt < 8; ++nt) {
                s[nt][0] = ex2f(s[nt][0] - m_[0]);
                s[nt][1] = ex2f(s[nt][1] - m_[0]);
                s[nt][2] = ex2f(s[nt][2] - m_[1]);
                s[nt][3] = ex2f(s[nt][3] - m_[1]);
                rs0 += s[nt][0] + s[nt][1];
                rs1 += s[nt][2] + s[nt][3];
            }
            rs0 += __shfl_xor_sync(0xffffffffu, rs0, 1);
            rs0 += __shfl_xor_sync(0xffffffffu, rs0, 2);
            rs1 += __shfl_xor_sync(0xffffffffu, rs1, 1);
            rs1 += __shfl_xor_sync(0xffffffffu, rs1, 2);
            l_[0] += rs0;
            l_[1] += rs1;

            #pragma unroll
            for (int j = 0; j < 4; ++j) {
                uint32_t pa[4];
                pa[0] = h2u(s[2*j][0],   s[2*j][1]);
                pa[1] = h2u(s[2*j][2],   s[2*j][3]);
                pa[2] = h2u(s[2*j+1][0], s[2*j+1][1]);
                pa[3] = h2u(s[2*j+1][2], s[2*j+1][3]);

                const uint32_t abase = (kbase + j * 16 + vrow) * AV_ROWB + vcol * 2;
                #pragma unroll
                for (int dg = 0; dg < 4; ++dg) {
                    uint32_t bv[4];
                    ldsm_x4_t(bv, v_b + abase + dg * 32);
                    mma_f16(oacc[dg * 2 + 0], pa, bv + 0);
                    mma_f16(oacc[dg * 2 + 1], pa, bv + 2);
                }
            }
        }
        __syncthreads();
    }

    const float inv0 = 1.f / l_[0], inv1 = 1.f / l_[1];
    #pragma unroll
    for (int dt = 0; dt < 8; ++dt) {
        const size_t d = (size_t)hoff + dt * 8 + kc;
        const size_t rowA = (size_t)(q0w + r) * DMODEL + d;
        const size_t rowB = (size_t)(q0w + r + 8) * DMODEL + d;
        float2 a0 = { oacc[dt][0] * inv0, oacc[dt][1] * inv0 };
        float2 a1 = { oacc[dt][2] * inv1, oacc[dt][3] * inv1 };
        *(float2*)(g_ctx + rowA) = a0;
        *(float2*)(g_ctx + rowB) = a1;
    }
}

// ======================= host launcher =======================
extern "C" void kernel_launch(void* const* d_in, const int* in_sizes, int n_in,
                              void* d_out, int out_size)
{
    (void)in_sizes; (void)n_in; (void)out_size;
    const float* x  = (const float*)d_in[0];
    const float* Wq = (const float*)d_in[2];
    const float* bq = (const float*)d_in[3];
    const float* Wk = (const float*)d_in[4];
    const float* bk = (const float*)d_in[5];
    const float* Wv = (const float*)d_in[6];
    const float* bv = (const float*)d_in[7];
    const float* Wo = (const float*)d_in[8];
    const float* bo = (const float*)d_in[9];
    float* out = (float*)d_out;

    int8_t *x1, *x2, *c1, *c2;
    float *sx, *sc, *ctx;
    cudaGetSymbolAddress((void**)&x1, g_x1);
    cudaGetSymbolAddress((void**)&x2, g_x2);
    cudaGetSymbolAddress((void**)&sx, g_sx);
    cudaGetSymbolAddress((void**)&c1, g_c1);
    cudaGetSymbolAddress((void**)&c2, g_c2);
    cudaGetSymbolAddress((void**)&sc, g_sc);
    cudaGetSymbolAddress((void**)&ctx, g_ctx);

    cudaFuncSetAttribute(gemm_qkv_kernel,
                         cudaFuncAttributeMaxDynamicSharedMemorySize, QGEMM_SMEM);
    cudaFuncSetAttribute(gemm_o_kernel,
                         cudaFuncAttributeMaxDynamicSharedMemorySize, QGEMM_SMEM);
    cudaFuncSetAttribute(attn_kernel,
                         cudaFuncAttributeMaxDynamicSharedMemorySize, ATT_SMEM);

    // 1: weight column max
    colmax4_kernel<<<dim3(8, 4), 1024>>>(Wq, Wk, Wv, Wo);
    // 2: weight transpose + quant
    transpose_quant4_kernel<<<dim3(32, 32, 4), 256>>>(Wq, Wk, Wv, Wo);
    // 3: input row-quant
    rowquant_kernel<<<S_LEN, 256>>>(x, x1, x2, sx);
    // 4: fused Q/K/V projections  (profiled slot)
    gemm_qkv_kernel<<<dim3(16, 32, 3), 256, QGEMM_SMEM>>>(bq, bk, bv);
    // 5: attention
    attn_kernel<<<dim3(S_LEN / 128, NHEADS), 256, ATT_SMEM>>>();
    // 6: ctx row-quant
    rowquant_kernel<<<S_LEN, 256>>>(ctx, c1, c2, sc);
    // 7: O projection
    gemm_o_kernel<<<dim3(16, 32), 256, QGEMM_SMEM>>>(bo, out);
}

// round 15
// speedup vs baseline: 1.3471x; 1.0363x over previous
#include <cuda_runtime.h>
#include <cuda_bf16.h>
#include <cuda_fp16.h>
#include <cstdint>
#include <math.h>

#define S_LEN  4096
#define DMODEL 1024
#define NHEADS 16
#define DK     64

// ======================= scratch (device globals) =======================
__device__ int8_t g_x1[(size_t)S_LEN * DMODEL];
__device__ int8_t g_x2[(size_t)S_LEN * DMODEL];
__device__ float  g_sx[S_LEN];

__device__ int8_t g_wq1[(size_t)DMODEL * DMODEL];
__device__ int8_t g_wq2[(size_t)DMODEL * DMODEL];
__device__ int8_t g_wk1[(size_t)DMODEL * DMODEL];
__device__ int8_t g_wk2[(size_t)DMODEL * DMODEL];
__device__ int8_t g_wv1[(size_t)DMODEL * DMODEL];
__device__ int8_t g_wv2[(size_t)DMODEL * DMODEL];
__device__ int8_t g_wo1[(size_t)DMODEL * DMODEL];
__device__ int8_t g_wo2[(size_t)DMODEL * DMODEL];
__device__ unsigned g_wbits[4 * DMODEL];

// attention operands
__device__ int8_t g_q1[(size_t)S_LEN * DMODEL];
__device__ int8_t g_q2[(size_t)S_LEN * DMODEL];
__device__ int8_t g_k1[(size_t)S_LEN * DMODEL];
__device__ int8_t g_k2[(size_t)S_LEN * DMODEL];
__device__ float  g_sq[NHEADS * S_LEN];
__device__ float  g_sk[NHEADS * S_LEN];
__device__ __half g_v16[(size_t)S_LEN * DMODEL];

__device__ float  g_ctx[(size_t)S_LEN * DMODEL];
__device__ int8_t g_c1[(size_t)S_LEN * DMODEL];
__device__ int8_t g_c2[(size_t)S_LEN * DMODEL];
__device__ float  g_sc[S_LEN];

// ======================= helpers =======================
__device__ __forceinline__ uint32_t smem_u32(const void* p) {
    uint32_t a;
    asm("{ .reg .u64 t; cvta.to.shared.u64 t, %1; cvt.u32.u64 %0, t; }" : "=r"(a) : "l"(p));
    return a;
}
__device__ __forceinline__ void cp16(uint32_t saddr, const void* g) {
    asm volatile("cp.async.ca.shared.global [%0], [%1], 16;" :: "r"(saddr), "l"(g));
}
__device__ __forceinline__ void cp_commit() { asm volatile("cp.async.commit_group;"); }
__device__ __forceinline__ void cp_wait1()  { asm volatile("cp.async.wait_group 1;"); }
__device__ __forceinline__ void cp_wait0()  { asm volatile("cp.async.wait_group 0;"); }

__device__ __forceinline__ void ldsm_x4(uint32_t* r, uint32_t addr) {
    asm volatile("ldmatrix.sync.aligned.m8n8.x4.shared.b16 {%0,%1,%2,%3}, [%4];"
                 : "=r"(r[0]), "=r"(r[1]), "=r"(r[2]), "=r"(r[3]) : "r"(addr));
}
__device__ __forceinline__ void ldsm_x4_t(uint32_t* r, uint32_t addr) {
    asm volatile("ldmatrix.sync.aligned.m8n8.x4.trans.shared.b16 {%0,%1,%2,%3}, [%4];"
                 : "=r"(r[0]), "=r"(r[1]), "=r"(r[2]), "=r"(r[3]) : "r"(addr));
}
__device__ __forceinline__ void mma_s8(int* c, const uint32_t* a, const uint32_t* b) {
    asm volatile(
        "mma.sync.aligned.m16n8k32.row.col.s32.s8.s8.s32 "
        "{%0,%1,%2,%3}, {%4,%5,%6,%7}, {%8,%9}, {%0,%1,%2,%3};"
        : "+r"(c[0]), "+r"(c[1]), "+r"(c[2]), "+r"(c[3])
        : "r"(a[0]), "r"(a[1]), "r"(a[2]), "r"(a[3]), "r"(b[0]), "r"(b[1]));
}
__device__ __forceinline__ void mma_f16(float* c, const uint32_t* a, const uint32_t* b) {
    asm volatile(
        "mma.sync.aligned.m16n8k16.row.col.f32.f16.f16.f32 "
        "{%0,%1,%2,%3}, {%4,%5,%6,%7}, {%8,%9}, {%0,%1,%2,%3};"
        : "+f"(c[0]), "+f"(c[1]), "+f"(c[2]), "+f"(c[3])
        : "r"(a[0]), "r"(a[1]), "r"(a[2]), "r"(a[3]), "r"(b[0]), "r"(b[1]));
}
__device__ __forceinline__ float ex2f(float x) {
    float y;
    asm("ex2.approx.f32 %0, %1;" : "=f"(y) : "f"(x));
    return y;
}
__device__ __forceinline__ uint32_t h2u(float x, float y) {
    __half2 h = __floats2half2_rn(x, y);
    return *(uint32_t*)&h;
}
__device__ __forceinline__ void digits2(float alpha, int& d1, int& d2) {
    d1 = __float2int_rn(alpha);
    d2 = __float2int_rn((alpha - (float)d1) * 254.f);
}
__device__ __forceinline__ uint32_t pack_dig(float a, float b, uint32_t& w2) {
    int a1, a2, b1, b2;
    digits2(a, a1, a2);
    digits2(b, b1, b2);
    w2 = (uint32_t)(a2 & 0xff) | (((uint32_t)(b2 & 0xff)) << 8);
    return (uint32_t)(a1 & 0xff) | (((uint32_t)(b1 & 0xff)) << 8);
}
__device__ __forceinline__ uint32_t pack4b(int a, int b, int c, int d) {
    return (uint32_t)(a & 0xff) | (((uint32_t)(b & 0xff)) << 8) |
           (((uint32_t)(c & 0xff)) << 16) | (((uint32_t)(d & 0xff)) << 24);
}

// ======================= weight prep =======================
__global__ __launch_bounds__(1024)
void colmax4_kernel(const float* __restrict__ Wq, const float* __restrict__ Wk,
                    const float* __restrict__ Wv, const float* __restrict__ Wo)
{
    const int z = blockIdx.y;
    const float* W = (z == 0) ? Wq : (z == 1) ? Wk : (z == 2) ? Wv : Wo;
    unsigned* bits = g_wbits + z * DMODEL;

    const int tid  = threadIdx.x;
    const int col  = blockIdx.x * 128 + (tid & 127);
    const int part = tid >> 7;

    float m = 0.f;
    #pragma unroll 8
    for (int r = part; r < DMODEL; r += 8)
        m = fmaxf(m, fabsf(W[(size_t)r * DMODEL + col]));

    __shared__ float red[8][128];
    red[part][tid & 127] = m;
    __syncthreads();
    if (tid < 128) {
        float mm = red[0][tid];
        #pragma unroll
        for (int i = 1; i < 8; ++i) mm = fmaxf(mm, red[i][tid]);
        bits[blockIdx.x * 128 + tid] = __float_as_uint(fmaxf(mm, 1e-30f));
    }
}

__global__ __launch_bounds__(256)
void transpose_quant4_kernel(const float* __restrict__ W0, const float* __restrict__ W1,
                             const float* __restrict__ W2, const float* __restrict__ W3)
{
    const int z = blockIdx.z;
    const float* W = (z == 0) ? W0 : (z == 1) ? W1 : (z == 2) ? W2 : W3;
    int8_t* B1 = (z == 0) ? g_wq1 : (z == 1) ? g_wk1 : (z == 2) ? g_wv1 : g_wo1;
    int8_t* B2 = (z == 0) ? g_wq2 : (z == 1) ? g_wk2 : (z == 2) ? g_wv2 : g_wo2;
    const unsigned* b = g_wbits + z * DMODEL;

    __shared__ float t[32][33];
    const int n0 = blockIdx.x * 32, k0 = blockIdx.y * 32;
    const int lx = threadIdx.x & 31, ly = threadIdx.x >> 5;
    #pragma unroll
    for (int i = 0; i < 32; i += 8)
        t[ly + i][lx] = W[(size_t)(k0 + ly + i) * DMODEL + n0 + lx];
    __syncthreads();
    #pragma unroll
    for (int i = 0; i < 32; i += 8) {
        const int n = n0 + ly + i;
        const float inv = 127.f / __uint_as_float(b[n]);
        int d1, d2;
        digits2(t[lx][ly + i] * inv, d1, d2);
        const size_t o = (size_t)n * DMODEL + k0 + lx;
        B1[o] = (int8_t)d1;
        B2[o] = (int8_t)d2;
    }
}

__global__ __launch_bounds__(256)
void rowquant_kernel(const float* __restrict__ src,
                     int8_t* __restrict__ D1, int8_t* __restrict__ D2,
                     float* __restrict__ s)
{
    const int row = blockIdx.x;
    const int tid = threadIdx.x;
    const float4 v = ((const float4*)(src + (size_t)row * DMODEL))[tid];
    float m = fmaxf(fmaxf(fabsf(v.x), fabsf(v.y)), fmaxf(fabsf(v.z), fabsf(v.w)));
    #pragma unroll
    for (int o = 16; o >= 1; o >>= 1)
        m = fmaxf(m, __shfl_xor_sync(0xffffffffu, m, o));
    __shared__ float red[8];
    if ((tid & 31) == 0) red[tid >> 5] = m;
    __syncthreads();
    float mm = red[0];
    #pragma unroll
    for (int i = 1; i < 8; i++) mm = fmaxf(mm, red[i]);
    mm = fmaxf(mm, 1e-30f);
    if (tid == 0) s[row] = mm * (1.f / 127.f);
    const float inv = 127.f / mm;
    int d1, d2;
    char4 c1, c2;
    digits2(v.x * inv, d1, d2); c1.x = (char)d1; c2.x = (char)d2;
    digits2(v.y * inv, d1, d2); c1.y = (char)d1; c2.y = (char)d2;
    digits2(v.z * inv, d1, d2); c1.z = (char)d1; c2.z = (char)d2;
    digits2(v.w * inv, d1, d2); c1.w = (char)d1; c2.w = (char)d2;
    ((char4*)(D1 + (size_t)row * DMODEL))[tid] = c1;
    ((char4*)(D2 + (size_t)row * DMODEL))[tid] = c2;
}

// ======================= int8 dual-digit GEMM, 128x64 tile, 4m x 2n warps =======================
// warp tile 32 rows x 32 cols; acc = 64 int regs; 2 CTAs/SM.
#define QBK 64
#define QNCH (DMODEL / QBK)
#define QROWB 80
#define QARR_A (128 * QROWB)             // 10240 per A digit
#define QARR_B2 (64 * QROWB)             // 5120 per B digit
#define QBOFF (2 * QARR_A)
#define QSTAGE_B (2 * QARR_A + 2 * QARR_B2)   // 30720
#define QGEMM_SMEM (2 * QSTAGE_B)        // 61440

struct GemmAcc { int a1[2][4][4]; int a2[2][4][4]; };   // [mi][nt2*2+hf][4]

__device__ __forceinline__ void gemm_mainloop64(
    const int8_t* A1p, const int8_t* A2p, const int8_t* B1p, const int8_t* B2p,
    uint32_t sbase, int tid, int lane, int wm0, int wn0, GemmAcc& acc)
{
    #pragma unroll
    for (int i = 0; i < 2; i++)
        #pragma unroll
        for (int j = 0; j < 4; j++)
            #pragma unroll
            for (int q = 0; q < 4; q++) { acc.a1[i][j][q] = 0; acc.a2[i][j][q] = 0; }

    const int a_row = lane & 15;
    const int a_kb  = (lane >> 4) * 16;
    const int b_row = ((lane >> 4) << 3) + (lane & 7);
    const int b_kb  = ((lane >> 3) & 1) * 16;

    auto issue_loads = [&](int c, int stage) {
        const int k0 = c * QBK;
        const uint32_t sb = sbase + stage * QSTAGE_B;
        #pragma unroll
        for (int jj = 0; jj < 2; jj++) {
            const int slot = tid + jj * 256;
            const int row = slot >> 2, col = slot & 3;
            cp16(sb + 0 * QARR_A + row * QROWB + col * 16,
                 A1p + (size_t)row * DMODEL + k0 + col * 16);
            cp16(sb + 1 * QARR_A + row * QROWB + col * 16,
                 A2p + (size_t)row * DMODEL + k0 + col * 16);
        }
        {
            const int row = tid >> 2, col = tid & 3;
            cp16(sb + QBOFF + 0 * QARR_B2 + row * QROWB + col * 16,
                 B1p + (size_t)row * DMODEL + k0 + col * 16);
            cp16(sb + QBOFF + 1 * QARR_B2 + row * QROWB + col * 16,
                 B2p + (size_t)row * DMODEL + k0 + col * 16);
        }
    };

    issue_loads(0, 0);
    cp_commit();

    for (int c = 0; c < QNCH; ++c) {
        const int stage = c & 1;
        const bool hasNext = (c + 1 < QNCH);
        if (hasNext) { issue_loads(c + 1, stage ^ 1); cp_commit(); }
        if (hasNext) cp_wait1(); else cp_wait0();
        __syncthreads();

        const uint32_t sb = sbase + stage * QSTAGE_B;
        #pragma unroll
        for (int ks = 0; ks < 2; ++ks) {
            const int kb = ks * 32;
            uint32_t fa1[2][4], fa2[2][4];
            #pragma unroll
            for (int mi = 0; mi < 2; ++mi) {
                const uint32_t aoff = (uint32_t)(wm0 + mi * 16 + a_row) * QROWB + kb + a_kb;
                ldsm_x4(fa1[mi], sb + 0 * QARR_A + aoff);
                ldsm_x4(fa2[mi], sb + 1 * QARR_A + aoff);
            }
            #pragma unroll
            for (int nt2 = 0; nt2 < 2; ++nt2) {
                const uint32_t boff = QBOFF + (uint32_t)(wn0 + nt2 * 16 + b_row) * QROWB + kb + b_kb;
                uint32_t fb1[4], fb2[4];
                ldsm_x4(fb1, sb + 0 * QARR_B2 + boff);
                ldsm_x4(fb2, sb + 1 * QARR_B2 + boff);
                #pragma unroll
                for (int mi = 0; mi < 2; ++mi) {
                    #pragma unroll
                    for (int hf = 0; hf < 2; ++hf) {
                        mma_s8(acc.a1[mi][nt2 * 2 + hf], fa1[mi], fb1 + hf * 2);
                        mma_s8(acc.a2[mi][nt2 * 2 + hf], fa1[mi], fb2 + hf * 2);
                        mma_s8(acc.a2[mi][nt2 * 2 + hf], fa2[mi], fb1 + hf * 2);
                    }
                }
            }
        }
        __syncthreads();
    }
}

// fused Q/K/V projection: grid (16, 32, 3), 2 CTAs/SM
__global__ __launch_bounds__(256, 2)
void gemm_qkv_kernel(const float* __restrict__ bq,
                     const float* __restrict__ bk,
                     const float* __restrict__ bv)
{
    extern __shared__ char sm[];
    const uint32_t sbase = smem_u32(sm);
    const int tid  = threadIdx.x;
    const int lane = tid & 31;
    const int wid  = tid >> 5;
    const int wm0  = (wid & 3) * 32;
    const int wn   = wid >> 2;          // 0..1
    const int wn0  = wn * 32;
    const int bm   = blockIdx.y * 128;
    const int bn   = blockIdx.x * 64;
    const int z    = blockIdx.z;

    const int8_t* B1 = (z == 0) ? g_wq1 : (z == 1) ? g_wk1 : g_wv1;
    const int8_t* B2 = (z == 0) ? g_wq2 : (z == 1) ? g_wk2 : g_wv2;
    const float* bias = (z == 0) ? bq : (z == 1) ? bk : bv;
    const unsigned* sBbits = g_wbits + z * DMODEL;

    GemmAcc acc;
    gemm_mainloop64(g_x1 + (size_t)bm * DMODEL, g_x2 + (size_t)bm * DMODEL,
                    B1 + (size_t)bn * DMODEL, B2 + (size_t)bn * DMODEL,
                    sbase, tid, lane, wm0, wn0, acc);

    const int erow = lane >> 2;
    const int ecol = (lane & 3) * 2;
    const float* sA = g_sx;

    if (z == 2) {
        // V: fp16 natural layout, per-element
        #pragma unroll
        for (int mi = 0; mi < 2; ++mi) {
            const int m0 = bm + wm0 + mi * 16 + erow;
            const float sa0 = sA[m0], sa8 = sA[m0 + 8];
            #pragma unroll
            for (int ni = 0; ni < 4; ++ni) {
                const int n = bn + wn0 + ni * 8 + ecol;
                const float sb0 = __uint_as_float(sBbits[n])     * (1.f / 127.f);
                const float sb1 = __uint_as_float(sBbits[n + 1]) * (1.f / 127.f);
                const float b0 = bias[n], b1 = bias[n + 1];
                const int* q1 = acc.a1[mi][ni];
                const int* q2 = acc.a2[mi][ni];
                const float c00 = ((float)q1[0] + (float)q2[0] * (1.f / 254.f)) * (sa0 * sb0) + b0;
                const float c01 = ((float)q1[1] + (float)q2[1] * (1.f / 254.f)) * (sa0 * sb1) + b1;
                const float c10 = ((float)q1[2] + (float)q2[2] * (1.f / 254.f)) * (sa8 * sb0) + b0;
                const float c11 = ((float)q1[3] + (float)q2[3] * (1.f / 254.f)) * (sa8 * sb1) + b1;
                *(uint32_t*)(g_v16 + (size_t)m0 * DMODEL + n)       = h2u(c00, c01);
                *(uint32_t*)(g_v16 + (size_t)(m0 + 8) * DMODEL + n) = h2u(c10, c11);
            }
        }
    } else {
        int8_t* D1 = z ? g_k1 : g_q1;
        int8_t* D2 = z ? g_k2 : g_q2;
        float* sOut = z ? g_sk : g_sq;
        const float smul = z ? 1.0f : 0.125f * 1.44269504f;
        const int head = bn >> 6;

        // dequant this warp's 32 cols for its 4 row-slots
        float vv[2][2][8];   // [mi][rowhalf][4 ni * 2]
        float pmx[2][2];
        #pragma unroll
        for (int mi = 0; mi < 2; ++mi) {
            const int m0 = bm + wm0 + mi * 16 + erow;
            const float sa0 = sA[m0], sa8 = sA[m0 + 8];
            float mx0 = 0.f, mx1 = 0.f;
            #pragma unroll
            for (int ni = 0; ni < 4; ++ni) {
                const int n = bn + wn0 + ni * 8 + ecol;
                const float sb0 = __uint_as_float(sBbits[n])     * (1.f / 127.f);
                const float sb1 = __uint_as_float(sBbits[n + 1]) * (1.f / 127.f);
                const float b0 = bias[n], b1 = bias[n + 1];
                const int* q1 = acc.a1[mi][ni];
                const int* q2 = acc.a2[mi][ni];
                const float c00 = ((float)q1[0] + (float)q2[0] * (1.f / 254.f)) * (sa0 * sb0) + b0;
                const float c01 = ((float)q1[1] + (float)q2[1] * (1.f / 254.f)) * (sa0 * sb1) + b1;
                const float c10 = ((float)q1[2] + (float)q2[2] * (1.f / 254.f)) * (sa8 * sb0) + b0;
                const float c11 = ((float)q1[3] + (float)q2[3] * (1.f / 254.f)) * (sa8 * sb1) + b1;
                vv[mi][0][ni * 2 + 0] = c00;  vv[mi][0][ni * 2 + 1] = c01;
                vv[mi][1][ni * 2 + 0] = c10;  vv[mi][1][ni * 2 + 1] = c11;
                mx0 = fmaxf(mx0, fmaxf(fabsf(c00), fabsf(c01)));
                mx1 = fmaxf(mx1, fmaxf(fabsf(c10), fabsf(c11)));
            }
            mx0 = fmaxf(mx0, __shfl_xor_sync(0xffffffffu, mx0, 1));
            mx0 = fmaxf(mx0, __shfl_xor_sync(0xffffffffu, mx0, 2));
            mx1 = fmaxf(mx1, __shfl_xor_sync(0xffffffffu, mx1, 1));
            mx1 = fmaxf(mx1, __shfl_xor_sync(0xffffffffu, mx1, 2));
            pmx[mi][0] = mx0;
            pmx[mi][1] = mx1;
        }

        // cross-warp max over the head's 64 cols (2 n-warps), via smem
        float* red = (float*)sm;   // 128 rows x 2 partials
        if ((lane & 3) == 0) {
            #pragma unroll
            for (int mi = 0; mi < 2; ++mi) {
                red[(wm0 + mi * 16 + erow) * 2 + wn]     = pmx[mi][0];
                red[(wm0 + mi * 16 + erow + 8) * 2 + wn] = pmx[mi][1];
            }
        }
        __syncthreads();

        #pragma unroll
        for (int mi = 0; mi < 2; ++mi) {
            const int m0 = bm + wm0 + mi * 16 + erow;
            const int r0 = wm0 + mi * 16 + erow;
            const float mx0 = fmaxf(fmaxf(red[r0 * 2], red[r0 * 2 + 1]), 1e-20f);
            const float mx1 = fmaxf(fmaxf(red[(r0 + 8) * 2], red[(r0 + 8) * 2 + 1]), 1e-20f);
            if (wn == 0 && (lane & 3) == 0) {
                sOut[head * S_LEN + m0]     = mx0 * (smul / 127.f);
                sOut[head * S_LEN + m0 + 8] = mx1 * (smul / 127.f);
            }
            const float i0 = 127.f / mx0, i1 = 127.f / mx1;
            #pragma unroll
            for (int ni = 0; ni < 4; ++ni) {
                const int n = bn + wn0 + ni * 8 + ecol;
                uint32_t w2;
                uint32_t w1 = pack_dig(vv[mi][0][ni * 2] * i0, vv[mi][0][ni * 2 + 1] * i0, w2);
                *(uint16_t*)(D1 + (size_t)m0 * DMODEL + n) = (uint16_t)w1;
                *(uint16_t*)(D2 + (size_t)m0 * DMODEL + n) = (uint16_t)w2;
                w1 = pack_dig(vv[mi][1][ni * 2] * i1, vv[mi][1][ni * 2 + 1] * i1, w2);
                *(uint16_t*)(D1 + (size_t)(m0 + 8) * DMODEL + n) = (uint16_t)w1;
                *(uint16_t*)(D2 + (size_t)(m0 + 8) * DMODEL + n) = (uint16_t)w2;
            }
        }
    }
}

// O projection: fp32 out + bias, grid (16, 32), 2 CTAs/SM
__global__ __launch_bounds__(256, 2)
void gemm_o_kernel(const float* __restrict__ bias, float* __restrict__ C)
{
    extern __shared__ char sm[];
    const uint32_t sbase = smem_u32(sm);
    const int tid  = threadIdx.x;
    const int lane = tid & 31;
    const int wid  = tid >> 5;
    const int wm0  = (wid & 3) * 32;
    const int wn0  = (wid >> 2) * 32;
    const int bm   = blockIdx.y * 128;
    const int bn   = blockIdx.x * 64;

    GemmAcc acc;
    gemm_mainloop64(g_c1 + (size_t)bm * DMODEL, g_c2 + (size_t)bm * DMODEL,
                    g_wo1 + (size_t)bn * DMODEL, g_wo2 + (size_t)bn * DMODEL,
                    sbase, tid, lane, wm0, wn0, acc);

    const unsigned* sBbits = g_wbits + 3 * DMODEL;
    const int erow = lane >> 2;
    const int ecol = (lane & 3) * 2;
    #pragma unroll
    for (int mi = 0; mi < 2; ++mi) {
        const int m0 = bm + wm0 + mi * 16 + erow;
        const float sa0 = g_sc[m0], sa8 = g_sc[m0 + 8];
        #pragma unroll
        for (int ni = 0; ni < 4; ++ni) {
            const int n = bn + wn0 + ni * 8 + ecol;
            const float sb0 = __uint_as_float(sBbits[n])     * (1.f / 127.f);
            const float sb1 = __uint_as_float(sBbits[n + 1]) * (1.f / 127.f);
            const float b0 = bias[n], b1 = bias[n + 1];
            const int* q1 = acc.a1[mi][ni];
            const int* q2 = acc.a2[mi][ni];
            float2 v0, v1;
            v0.x = ((float)q1[0] + (float)q2[0] * (1.f / 254.f)) * (sa0 * sb0) + b0;
            v0.y = ((float)q1[1] + (float)q2[1] * (1.f / 254.f)) * (sa0 * sb1) + b1;
            v1.x = ((float)q1[2] + (float)q2[2] * (1.f / 254.f)) * (sa8 * sb0) + b0;
            v1.y = ((float)q1[3] + (float)q2[3] * (1.f / 254.f)) * (sa8 * sb1) + b1;
            *(float2*)(C + (size_t)m0 * DMODEL + n)       = v0;
            *(float2*)(C + (size_t)(m0 + 8) * DMODEL + n) = v1;
        }
    }
}

// ======================= hybrid flash attention (unchanged) =======================
#define AK_ROWB 80
#define AK_B (128 * AK_ROWB)
#define AV_ROWB 144
#define AV_B (128 * AV_ROWB)
#define ASK_OFF (2 * AK_B + AV_B)
#define ABUF_B (ASK_OFF + 512)
#define ATT_SMEM (2 * ABUF_B)

__global__ __launch_bounds__(256, 2)
void attn_kernel()
{
    extern __shared__ char sm[];
    const uint32_t sbase = smem_u32(sm);

    const int tid  = threadIdx.x;
    const int lane = tid & 31;
    const int w    = tid >> 5;
    const int h    = blockIdx.y;
    const int qt   = (int)gridDim.x - 1 - (int)blockIdx.x;
    const int q0   = qt * 128;
    const int hoff = h * DK;
    const int q0w  = q0 + w * 16;

    const int r  = lane >> 2;
    const int kc = (lane & 3) * 2;

    uint32_t q1f[2][4], q2f[2][4];
    {
        const int qb = (lane & 3) * 4;
        #pragma unroll
        for (int g = 0; g < 2; ++g) {
            const size_t bA = (size_t)(q0w + r) * DMODEL + hoff + g * 32 + qb;
            const size_t bB = (size_t)(q0w + r + 8) * DMODEL + hoff + g * 32 + qb;
            q1f[g][0] = *(const uint32_t*)(g_q1 + bA);
            q1f[g][1] = *(const uint32_t*)(g_q1 + bB);
            q1f[g][2] = *(const uint32_t*)(g_q1 + bA + 16);
            q1f[g][3] = *(const uint32_t*)(g_q1 + bB + 16);
            q2f[g][0] = *(const uint32_t*)(g_q2 + bA);
            q2f[g][1] = *(const uint32_t*)(g_q2 + bB);
            q2f[g][2] = *(const uint32_t*)(g_q2 + bA + 16);
            q2f[g][3] = *(const uint32_t*)(g_q2 + bB + 16);
        }
    }
    const float sq0f = g_sq[h * S_LEN + q0w + r]     * (1.f / 254.f);
    const float sq1f = g_sq[h * S_LEN + q0w + r + 8] * (1.f / 254.f);

    auto issue_kv = [&](int kt, int buf) {
        const int k0 = kt * 128;
        const uint32_t sb = sbase + buf * ABUF_B;
        #pragma unroll
        for (int d = 0; d < 2; ++d) {
            const int8_t* src = (d ? g_k2 : g_k1) + (size_t)k0 * DMODEL + hoff;
            #pragma unroll
            for (int j = 0; j < 2; ++j) {
                const int slot = tid + j * 256;
                const int row = slot >> 2, col = slot & 3;
                cp16(sb + d * AK_B + row * AK_ROWB + col * 16,
                     src + (size_t)row * DMODEL + col * 16);
            }
        }
        {
            const __half* src = g_v16 + (size_t)k0 * DMODEL + hoff;
            #pragma unroll
            for (int j = 0; j < 4; ++j) {
                const int slot = tid + j * 256;
                const int row = slot >> 3, col = slot & 7;
                cp16(sb + 2 * AK_B + row * AV_ROWB + col * 16,
                     src + (size_t)row * DMODEL + col * 8);
            }
        }
        if (tid < 32)
            cp16(sb + ASK_OFF + tid * 16, g_sk + h * S_LEN + k0 + tid * 4);
    };

    float m_[2] = { -1e30f, -1e30f }, l_[2] = { 0.f, 0.f };
    float oacc[8][4];
    #pragma unroll
    for (int i = 0; i < 8; i++)
        #pragma unroll
        for (int j = 0; j < 4; j++) oacc[i][j] = 0.f;

    issue_kv(0, 0);
    cp_commit();

    const uint32_t b_off  = (uint32_t)(((lane >> 4) << 3) + (lane & 7));
    const uint32_t kb_off = ((lane >> 3) & 1) * 16;
    const uint32_t vrow   = lane & 15;
    const uint32_t vcol   = (lane >> 4) * 8;

    for (int kt = 0; kt <= qt; ++kt) {
        const int buf = kt & 1;
        const bool hasNext = kt < qt;
        if (hasNext) { issue_kv(kt + 1, buf ^ 1); cp_commit(); }
        if (hasNext) cp_wait1(); else cp_wait0();
        __syncthreads();

        const uint32_t k1b = sbase + buf * ABUF_B;
        const uint32_t k2b = k1b + AK_B;
        const uint32_t v_b = k1b + 2 * AK_B;
        const float* sks = (const float*)(sm + buf * ABUF_B + ASK_OFF);

        #pragma unroll
        for (int half = 0; half < 2; ++half) {
            if (kt == qt && half == 1 && (w * 16 + 15) < 64) break;

            const int kbase = half * 64;

            float s[8][4];
            #pragma unroll
            for (int nt2 = 0; nt2 < 4; ++nt2) {
                int a1[2][4] = { {0,0,0,0}, {0,0,0,0} };
                int a2[2][4] = { {0,0,0,0}, {0,0,0,0} };
                #pragma unroll
                for (int g = 0; g < 2; ++g) {
                    const uint32_t addr = (uint32_t)(kbase + nt2 * 16 + b_off) * AK_ROWB + g * 32 + kb_off;
                    uint32_t fb1[4], fb2[4];
                    ldsm_x4(fb1, k1b + addr);
                    ldsm_x4(fb2, k2b + addr);
                    #pragma unroll
                    for (int hf = 0; hf < 2; ++hf) {
                        mma_s8(a1[hf], q1f[g], fb1 + hf * 2);
                        mma_s8(a2[hf], q1f[g], fb2 + hf * 2);
                        mma_s8(a2[hf], q2f[g], fb1 + hf * 2);
                    }
                }
                #pragma unroll
                for (int hf = 0; hf < 2; ++hf) {
                    const float2 sk2 = *(const float2*)(sks + (kbase + (nt2 * 2 + hf) * 8) + kc);
                    s[nt2 * 2 + hf][0] = (float)(a1[hf][0] * 254 + a2[hf][0]) * (sq0f * sk2.x);
                    s[nt2 * 2 + hf][1] = (float)(a1[hf][1] * 254 + a2[hf][1]) * (sq0f * sk2.y);
                    s[nt2 * 2 + hf][2] = (float)(a1[hf][2] * 254 + a2[hf][2]) * (sq1f * sk2.x);
                    s[nt2 * 2 + hf][3] = (float)(a1[hf][3] * 254 + a2[hf][3]) * (sq1f * sk2.y);
                }
            }

            if (kt == qt) {
                #pragma unroll
                for (int nt = 0; nt < 8; ++nt) {
                    #pragma unroll
                    for (int c = 0; c < 4; ++c) {
                        const int key = kbase + nt * 8 + kc + (c & 1);
                        const int qq  = w * 16 + r + (c >> 1) * 8;
                        if (key > qq) s[nt][c] = -1e30f;
                    }
                }
            }

            float mx0 = -1e30f, mx1 = -1e30f;
            #pragma unroll
            for (int nt = 0; nt < 8; ++nt) {
                mx0 = fmaxf(mx0, fmaxf(s[nt][0], s[nt][1]));
                mx1 = fmaxf(mx1, fmaxf(s[nt][2], s[nt][3]));
            }
            mx0 = fmaxf(mx0, __shfl_xor_sync(0xffffffffu, mx0, 1));
            mx0 = fmaxf(mx0, __shfl_xor_sync(0xffffffffu, mx0, 2));
            mx1 = fmaxf(mx1, __shfl_xor_sync(0xffffffffu, mx1, 1));
            mx1 = fmaxf(mx1, __shfl_xor_sync(0xffffffffu, mx1, 2));

            const bool upd = (mx0 > m_[0]) || (mx1 > m_[1]);
            if (__any_sync(0xffffffffu, upd)) {
                const float nm0 = fmaxf(m_[0], mx0), nm1 = fmaxf(m_[1], mx1);
                const float al0 = ex2f(m_[0] - nm0), al1 = ex2f(m_[1] - nm1);
                l_[0] *= al0;  l_[1] *= al1;
                m_[0] = nm0;   m_[1] = nm1;
                #pragma unroll
                for (int dt = 0; dt < 8; ++dt) {
                    oacc[dt][0] *= al0; oacc[dt][1] *= al0;
                    oacc[dt][2] *= al1; oacc[dt][3] *= al1;
                }
            }

            float rs0 = 0.f, rs1 = 0.f;
            #pragma unroll
            for (int nt = 0; nt < 8; ++nt) {
                s[nt][0] = ex2f(s[nt][0] - m_[0]);
                s[nt][1] = ex2f(s[nt][1] - m_[0]);
                s[nt][2] = ex2f(s[nt][2] - m_[1]);
                s[nt][3] = ex2f(s[nt][3] - m_[1]);
                rs0 += s[nt][0] + s[nt][1];
                rs1 += s[nt][2] + s[nt][3];
            }
            rs0 += __shfl_xor_sync(0xffffffffu, rs0, 1);
            rs0 += __shfl_xor_sync(0xffffffffu, rs0, 2);
            rs1 += __shfl_xor_sync(0xffffffffu, rs1, 1);
            rs1 += __shfl_xor_sync(0xffffffffu, rs1, 2);
            l_[0] += rs0;
            l_[1] += rs1;

            #pragma unroll
            for (int j = 0; j < 4; ++j) {
                uint32_t pa[4];
                pa[0] = h2u(s[2*j][0],   s[2*j][1]);
                pa[1] = h2u(s[2*j][2],   s[2*j][3]);
                pa[2] = h2u(s[2*j+1][0], s[2*j+1][1]);
                pa[3] = h2u(s[2*j+1][2], s[2*j+1][3]);

                const uint32_t abase = (kbase + j * 16 + vrow) * AV_ROWB + vcol * 2;
                #pragma unroll
                for (int dg = 0; dg < 4; ++dg) {
                    uint32_t bv[4];
                    ldsm_x4_t(bv, v_b + abase + dg * 32);
                    mma_f16(oacc[dg * 2 + 0], pa, bv + 0);
                    mma_f16(oacc[dg * 2 + 1], pa, bv + 2);
                }
            }
        }
        __syncthreads();
    }

    const float inv0 = 1.f / l_[0], inv1 = 1.f / l_[1];
    #pragma unroll
    for (int dt = 0; dt < 8; ++dt) {
        const size_t d = (size_t)hoff + dt * 8 + kc;
        const size_t rowA = (size_t)(q0w + r) * DMODEL + d;
        const size_t rowB = (size_t)(q0w + r + 8) * DMODEL + d;
        float2 a0 = { oacc[dt][0] * inv0, oacc[dt][1] * inv0 };
        float2 a1 = { oacc[dt][2] * inv1, oacc[dt][3] * inv1 };
        *(float2*)(g_ctx + rowA) = a0;
        *(float2*)(g_ctx + rowB) = a1;
    }
}

// ======================= host launcher =======================
extern "C" void kernel_launch(void* const* d_in, const int* in_sizes, int n_in,
                              void* d_out, int out_size)
{
    (void)in_sizes; (void)n_in; (void)out_size;
    const float* x  = (const float*)d_in[0];
    const float* Wq = (const float*)d_in[2];
    const float* bq = (const float*)d_in[3];
    const float* Wk = (const float*)d_in[4];
    const float* bk = (const float*)d_in[5];
    const float* Wv = (const float*)d_in[6];
    const float* bv = (const float*)d_in[7];
    const float* Wo = (const float*)d_in[8];
    const float* bo = (const float*)d_in[9];
    float* out = (float*)d_out;

    int8_t *x1, *x2, *c1, *c2;
    float *sx, *sc, *ctx;
    cudaGetSymbolAddress((void**)&x1, g_x1);
    cudaGetSymbolAddress((void**)&x2, g_x2);
    cudaGetSymbolAddress((void**)&sx, g_sx);
    cudaGetSymbolAddress((void**)&c1, g_c1);
    cudaGetSymbolAddress((void**)&c2, g_c2);
    cudaGetSymbolAddress((void**)&sc, g_sc);
    cudaGetSymbolAddress((void**)&ctx, g_ctx);

    cudaFuncSetAttribute(gemm_qkv_kernel,
                         cudaFuncAttributeMaxDynamicSharedMemorySize, QGEMM_SMEM);
    cudaFuncSetAttribute(gemm_o_kernel,
                         cudaFuncAttributeMaxDynamicSharedMemorySize, QGEMM_SMEM);
    cudaFuncSetAttribute(attn_kernel,
                         cudaFuncAttributeMaxDynamicSharedMemorySize, ATT_SMEM);

    // 1: weight column max
    colmax4_kernel<<<dim3(8, 4), 1024>>>(Wq, Wk, Wv, Wo);
    // 2: weight transpose + quant
    transpose_quant4_kernel<<<dim3(32, 32, 4), 256>>>(Wq, Wk, Wv, Wo);
    // 3: input row-quant
    rowquant_kernel<<<S_LEN, 256>>>(x, x1, x2, sx);
    // 4: fused Q/K/V projections  (profiled slot)
    gemm_qkv_kernel<<<dim3(16, 32, 3), 256, QGEMM_SMEM>>>(bq, bk, bv);
    // 5: attention
    attn_kernel<<<dim3(S_LEN / 128, NHEADS), 256, ATT_SMEM>>>();
    // 6: ctx row-quant
    rowquant_kernel<<<S_LEN, 256>>>(ctx, c1, c2, sc);
    // 7: O projection
    gemm_o_kernel<<<dim3(16, 32), 256, QGEMM_SMEM>>>(bo, out);
}

// round 16
// speedup vs baseline: 1.3495x; 1.0018x over previous
#include <cuda_runtime.h>
#include <cuda_bf16.h>
#include <cuda_fp16.h>
#include <cstdint>
#include <math.h>

#define S_LEN  4096
#define DMODEL 1024
#define NHEADS 16
#define DK     64

// ======================= scratch (device globals) =======================
__device__ int8_t g_x1[(size_t)S_LEN * DMODEL];
__device__ int8_t g_x2[(size_t)S_LEN * DMODEL];
__device__ float  g_sx[S_LEN];

__device__ int8_t g_wq1[(size_t)DMODEL * DMODEL];
__device__ int8_t g_wq2[(size_t)DMODEL * DMODEL];
__device__ int8_t g_wk1[(size_t)DMODEL * DMODEL];
__device__ int8_t g_wk2[(size_t)DMODEL * DMODEL];
__device__ int8_t g_wv1[(size_t)DMODEL * DMODEL];
__device__ int8_t g_wv2[(size_t)DMODEL * DMODEL];
__device__ int8_t g_wo1[(size_t)DMODEL * DMODEL];
__device__ int8_t g_wo2[(size_t)DMODEL * DMODEL];
__device__ unsigned g_wbits[4 * DMODEL];

// attention operands
__device__ int8_t g_q1[(size_t)S_LEN * DMODEL];
__device__ int8_t g_q2[(size_t)S_LEN * DMODEL];
__device__ int8_t g_k1[(size_t)S_LEN * DMODEL];
__device__ int8_t g_k2[(size_t)S_LEN * DMODEL];
__device__ float  g_sq[NHEADS * S_LEN];
__device__ float  g_sk[NHEADS * S_LEN];
__device__ __half g_v16[(size_t)S_LEN * DMODEL];

__device__ float  g_ctx[(size_t)S_LEN * DMODEL];
__device__ int8_t g_c1[(size_t)S_LEN * DMODEL];
__device__ int8_t g_c2[(size_t)S_LEN * DMODEL];
__device__ float  g_sc[S_LEN];

// ======================= helpers =======================
__device__ __forceinline__ uint32_t smem_u32(const void* p) {
    uint32_t a;
    asm("{ .reg .u64 t; cvta.to.shared.u64 t, %1; cvt.u32.u64 %0, t; }" : "=r"(a) : "l"(p));
    return a;
}
__device__ __forceinline__ void cp16(uint32_t saddr, const void* g) {
    asm volatile("cp.async.ca.shared.global [%0], [%1], 16;" :: "r"(saddr), "l"(g));
}
__device__ __forceinline__ void cp_commit() { asm volatile("cp.async.commit_group;"); }
__device__ __forceinline__ void cp_wait1()  { asm volatile("cp.async.wait_group 1;"); }
__device__ __forceinline__ void cp_wait0()  { asm volatile("cp.async.wait_group 0;"); }

__device__ __forceinline__ void ldsm_x4(uint32_t* r, uint32_t addr) {
    asm volatile("ldmatrix.sync.aligned.m8n8.x4.shared.b16 {%0,%1,%2,%3}, [%4];"
                 : "=r"(r[0]), "=r"(r[1]), "=r"(r[2]), "=r"(r[3]) : "r"(addr));
}
__device__ __forceinline__ void ldsm_x4_t(uint32_t* r, uint32_t addr) {
    asm volatile("ldmatrix.sync.aligned.m8n8.x4.trans.shared.b16 {%0,%1,%2,%3}, [%4];"
                 : "=r"(r[0]), "=r"(r[1]), "=r"(r[2]), "=r"(r[3]) : "r"(addr));
}
__device__ __forceinline__ void mma_s8(int* c, const uint32_t* a, const uint32_t* b) {
    asm volatile(
        "mma.sync.aligned.m16n8k32.row.col.s32.s8.s8.s32 "
        "{%0,%1,%2,%3}, {%4,%5,%6,%7}, {%8,%9}, {%0,%1,%2,%3};"
        : "+r"(c[0]), "+r"(c[1]), "+r"(c[2]), "+r"(c[3])
        : "r"(a[0]), "r"(a[1]), "r"(a[2]), "r"(a[3]), "r"(b[0]), "r"(b[1]));
}
__device__ __forceinline__ void mma_f16(float* c, const uint32_t* a, const uint32_t* b) {
    asm volatile(
        "mma.sync.aligned.m16n8k16.row.col.f32.f16.f16.f32 "
        "{%0,%1,%2,%3}, {%4,%5,%6,%7}, {%8,%9}, {%0,%1,%2,%3};"
        : "+f"(c[0]), "+f"(c[1]), "+f"(c[2]), "+f"(c[3])
        : "r"(a[0]), "r"(a[1]), "r"(a[2]), "r"(a[3]), "r"(b[0]), "r"(b[1]));
}
__device__ __forceinline__ float ex2f(float x) {
    float y;
    asm("ex2.approx.f32 %0, %1;" : "=f"(y) : "f"(x));
    return y;
}
__device__ __forceinline__ uint32_t h2u(float x, float y) {
    __half2 h = __floats2half2_rn(x, y);
    return *(uint32_t*)&h;
}
__device__ __forceinline__ void digits2(float alpha, int& d1, int& d2) {
    d1 = __float2int_rn(alpha);
    d2 = __float2int_rn((alpha - (float)d1) * 254.f);
}
__device__ __forceinline__ uint32_t pack_dig(float a, float b, uint32_t& w2) {
    int a1, a2, b1, b2;
    digits2(a, a1, a2);
    digits2(b, b1, b2);
    w2 = (uint32_t)(a2 & 0xff) | (((uint32_t)(b2 & 0xff)) << 8);
    return (uint32_t)(a1 & 0xff) | (((uint32_t)(b1 & 0xff)) << 8);
}

// ======================= weight prep =======================
__global__ __launch_bounds__(1024)
void colmax4_kernel(const float* __restrict__ Wq, const float* __restrict__ Wk,
                    const float* __restrict__ Wv, const float* __restrict__ Wo)
{
    const int z = blockIdx.y;
    const float* W = (z == 0) ? Wq : (z == 1) ? Wk : (z == 2) ? Wv : Wo;
    unsigned* bits = g_wbits + z * DMODEL;

    const int tid  = threadIdx.x;
    const int col  = blockIdx.x * 128 + (tid & 127);
    const int part = tid >> 7;

    float m = 0.f;
    #pragma unroll 8
    for (int r = part; r < DMODEL; r += 8)
        m = fmaxf(m, fabsf(W[(size_t)r * DMODEL + col]));

    __shared__ float red[8][128];
    red[part][tid & 127] = m;
    __syncthreads();
    if (tid < 128) {
        float mm = red[0][tid];
        #pragma unroll
        for (int i = 1; i < 8; ++i) mm = fmaxf(mm, red[i][tid]);
        bits[blockIdx.x * 128 + tid] = __float_as_uint(fmaxf(mm, 1e-30f));
    }
}

// merged: weight transpose+quant (z 0..3) + input rowquant (z 4..7). grid (32,32,8)
__global__ __launch_bounds__(256)
void prep_combo_kernel(const float* __restrict__ W0, const float* __restrict__ W1,
                       const float* __restrict__ W2, const float* __restrict__ W3,
                       const float* __restrict__ x)
{
    __shared__ float t[32][33];
    const int z = blockIdx.z;

    if (z < 4) {
        const float* W = (z == 0) ? W0 : (z == 1) ? W1 : (z == 2) ? W2 : W3;
        int8_t* B1 = (z == 0) ? g_wq1 : (z == 1) ? g_wk1 : (z == 2) ? g_wv1 : g_wo1;
        int8_t* B2 = (z == 0) ? g_wq2 : (z == 1) ? g_wk2 : (z == 2) ? g_wv2 : g_wo2;
        const unsigned* b = g_wbits + z * DMODEL;

        const int n0 = blockIdx.x * 32, k0 = blockIdx.y * 32;
        const int lx = threadIdx.x & 31, ly = threadIdx.x >> 5;
        #pragma unroll
        for (int i = 0; i < 32; i += 8)
            t[ly + i][lx] = W[(size_t)(k0 + ly + i) * DMODEL + n0 + lx];
        __syncthreads();
        #pragma unroll
        for (int i = 0; i < 32; i += 8) {
            const int n = n0 + ly + i;
            const float inv = 127.f / __uint_as_float(b[n]);
            int d1, d2;
            digits2(t[lx][ly + i] * inv, d1, d2);
            const size_t o = (size_t)n * DMODEL + k0 + lx;
            B1[o] = (int8_t)d1;
            B2[o] = (int8_t)d2;
        }
    } else {
        const int row = (z - 4) * 1024 + blockIdx.y * 32 + blockIdx.x;
        const int tid = threadIdx.x;
        const float4 v = ((const float4*)(x + (size_t)row * DMODEL))[tid];
        float m = fmaxf(fmaxf(fabsf(v.x), fabsf(v.y)), fmaxf(fabsf(v.z), fabsf(v.w)));
        #pragma unroll
        for (int o = 16; o >= 1; o >>= 1)
            m = fmaxf(m, __shfl_xor_sync(0xffffffffu, m, o));
        float* red = &t[0][0];
        if ((tid & 31) == 0) red[tid >> 5] = m;
        __syncthreads();
        float mm = red[0];
        #pragma unroll
        for (int i = 1; i < 8; i++) mm = fmaxf(mm, red[i]);
        mm = fmaxf(mm, 1e-30f);
        if (tid == 0) g_sx[row] = mm * (1.f / 127.f);
        const float inv = 127.f / mm;
        int d1, d2;
        char4 c1, c2;
        digits2(v.x * inv, d1, d2); c1.x = (char)d1; c2.x = (char)d2;
        digits2(v.y * inv, d1, d2); c1.y = (char)d1; c2.y = (char)d2;
        digits2(v.z * inv, d1, d2); c1.z = (char)d1; c2.z = (char)d2;
        digits2(v.w * inv, d1, d2); c1.w = (char)d1; c2.w = (char)d2;
        ((char4*)(g_x1 + (size_t)row * DMODEL))[tid] = c1;
        ((char4*)(g_x2 + (size_t)row * DMODEL))[tid] = c2;
    }
}

__global__ __launch_bounds__(256)
void rowquant_kernel(const float* __restrict__ src,
                     int8_t* __restrict__ D1, int8_t* __restrict__ D2,
                     float* __restrict__ s)
{
    const int row = blockIdx.x;
    const int tid = threadIdx.x;
    const float4 v = ((const float4*)(src + (size_t)row * DMODEL))[tid];
    float m = fmaxf(fmaxf(fabsf(v.x), fabsf(v.y)), fmaxf(fabsf(v.z), fabsf(v.w)));
    #pragma unroll
    for (int o = 16; o >= 1; o >>= 1)
        m = fmaxf(m, __shfl_xor_sync(0xffffffffu, m, o));
    __shared__ float red[8];
    if ((tid & 31) == 0) red[tid >> 5] = m;
    __syncthreads();
    float mm = red[0];
    #pragma unroll
    for (int i = 1; i < 8; i++) mm = fmaxf(mm, red[i]);
    mm = fmaxf(mm, 1e-30f);
    if (tid == 0) s[row] = mm * (1.f / 127.f);
    const float inv = 127.f / mm;
    int d1, d2;
    char4 c1, c2;
    digits2(v.x * inv, d1, d2); c1.x = (char)d1; c2.x = (char)d2;
    digits2(v.y * inv, d1, d2); c1.y = (char)d1; c2.y = (char)d2;
    digits2(v.z * inv, d1, d2); c1.z = (char)d1; c2.z = (char)d2;
    digits2(v.w * inv, d1, d2); c1.w = (char)d1; c2.w = (char)d2;
    ((char4*)(D1 + (size_t)row * DMODEL))[tid] = c1;
    ((char4*)(D2 + (size_t)row * DMODEL))[tid] = c2;
}

// ======================= int8 dual-digit GEMM, 128x64 tile, 4m x 2n warps =======================
#define QBK 64
#define QNCH (DMODEL / QBK)
#define QROWB 80
#define QARR_A (128 * QROWB)
#define QARR_B2 (64 * QROWB)
#define QBOFF (2 * QARR_A)
#define QSTAGE_B (2 * QARR_A + 2 * QARR_B2)
#define QGEMM_SMEM (2 * QSTAGE_B)

struct GemmAcc { int a1[2][4][4]; int a2[2][4][4]; };

__device__ __forceinline__ void gemm_mainloop64(
    const int8_t* A1p, const int8_t* A2p, const int8_t* B1p, const int8_t* B2p,
    uint32_t sbase, int tid, int lane, int wm0, int wn0, GemmAcc& acc)
{
    #pragma unroll
    for (int i = 0; i < 2; i++)
        #pragma unroll
        for (int j = 0; j < 4; j++)
            #pragma unroll
            for (int q = 0; q < 4; q++) { acc.a1[i][j][q] = 0; acc.a2[i][j][q] = 0; }

    const int a_row = lane & 15;
    const int a_kb  = (lane >> 4) * 16;
    const int b_row = ((lane >> 4) << 3) + (lane & 7);
    const int b_kb  = ((lane >> 3) & 1) * 16;

    auto issue_loads = [&](int c, int stage) {
        const int k0 = c * QBK;
        const uint32_t sb = sbase + stage * QSTAGE_B;
        #pragma unroll
        for (int jj = 0; jj < 2; jj++) {
            const int slot = tid + jj * 256;
            const int row = slot >> 2, col = slot & 3;
            cp16(sb + 0 * QARR_A + row * QROWB + col * 16,
                 A1p + (size_t)row * DMODEL + k0 + col * 16);
            cp16(sb + 1 * QARR_A + row * QROWB + col * 16,
                 A2p + (size_t)row * DMODEL + k0 + col * 16);
        }
        {
            const int row = tid >> 2, col = tid & 3;
            cp16(sb + QBOFF + 0 * QARR_B2 + row * QROWB + col * 16,
                 B1p + (size_t)row * DMODEL + k0 + col * 16);
            cp16(sb + QBOFF + 1 * QARR_B2 + row * QROWB + col * 16,
                 B2p + (size_t)row * DMODEL + k0 + col * 16);
        }
    };

    issue_loads(0, 0);
    cp_commit();

    for (int c = 0; c < QNCH; ++c) {
        const int stage = c & 1;
        const bool hasNext = (c + 1 < QNCH);
        if (hasNext) { issue_loads(c + 1, stage ^ 1); cp_commit(); }
        if (hasNext) cp_wait1(); else cp_wait0();
        __syncthreads();

        const uint32_t sb = sbase + stage * QSTAGE_B;
        #pragma unroll
        for (int ks = 0; ks < 2; ++ks) {
            const int kb = ks * 32;
            uint32_t fa1[2][4], fa2[2][4];
            #pragma unroll
            for (int mi = 0; mi < 2; ++mi) {
                const uint32_t aoff = (uint32_t)(wm0 + mi * 16 + a_row) * QROWB + kb + a_kb;
                ldsm_x4(fa1[mi], sb + 0 * QARR_A + aoff);
                ldsm_x4(fa2[mi], sb + 1 * QARR_A + aoff);
            }
            #pragma unroll
            for (int nt2 = 0; nt2 < 2; ++nt2) {
                const uint32_t boff = QBOFF + (uint32_t)(wn0 + nt2 * 16 + b_row) * QROWB + kb + b_kb;
                uint32_t fb1[4], fb2[4];
                ldsm_x4(fb1, sb + 0 * QARR_B2 + boff);
                ldsm_x4(fb2, sb + 1 * QARR_B2 + boff);
                #pragma unroll
                for (int mi = 0; mi < 2; ++mi) {
                    #pragma unroll
                    for (int hf = 0; hf < 2; ++hf) {
                        mma_s8(acc.a1[mi][nt2 * 2 + hf], fa1[mi], fb1 + hf * 2);
                        mma_s8(acc.a2[mi][nt2 * 2 + hf], fa1[mi], fb2 + hf * 2);
                        mma_s8(acc.a2[mi][nt2 * 2 + hf], fa2[mi], fb1 + hf * 2);
                    }
                }
            }
        }
        __syncthreads();
    }
}

// fused Q/K/V projection: grid (16, 32, 3), 2 CTAs/SM
__global__ __launch_bounds__(256, 2)
void gemm_qkv_kernel(const float* __restrict__ bq,
                     const float* __restrict__ bk,
                     const float* __restrict__ bv)
{
    extern __shared__ char sm[];
    const uint32_t sbase = smem_u32(sm);
    const int tid  = threadIdx.x;
    const int lane = tid & 31;
    const int wid  = tid >> 5;
    const int wm0  = (wid & 3) * 32;
    const int wn   = wid >> 2;
    const int wn0  = wn * 32;
    const int bm   = blockIdx.y * 128;
    const int bn   = blockIdx.x * 64;
    const int z    = blockIdx.z;

    const int8_t* B1 = (z == 0) ? g_wq1 : (z == 1) ? g_wk1 : g_wv1;
    const int8_t* B2 = (z == 0) ? g_wq2 : (z == 1) ? g_wk2 : g_wv2;
    const float* bias = (z == 0) ? bq : (z == 1) ? bk : bv;
    const unsigned* sBbits = g_wbits + z * DMODEL;

    GemmAcc acc;
    gemm_mainloop64(g_x1 + (size_t)bm * DMODEL, g_x2 + (size_t)bm * DMODEL,
                    B1 + (size_t)bn * DMODEL, B2 + (size_t)bn * DMODEL,
                    sbase, tid, lane, wm0, wn0, acc);

    const int erow = lane >> 2;
    const int ecol = (lane & 3) * 2;
    const float* sA = g_sx;

    if (z == 2) {
        #pragma unroll
        for (int mi = 0; mi < 2; ++mi) {
            const int m0 = bm + wm0 + mi * 16 + erow;
            const float sa0 = sA[m0], sa8 = sA[m0 + 8];
            #pragma unroll
            for (int ni = 0; ni < 4; ++ni) {
                const int n = bn + wn0 + ni * 8 + ecol;
                const float sb0 = __uint_as_float(sBbits[n])     * (1.f / 127.f);
                const float sb1 = __uint_as_float(sBbits[n + 1]) * (1.f / 127.f);
                const float b0 = bias[n], b1 = bias[n + 1];
                const int* q1 = acc.a1[mi][ni];
                const int* q2 = acc.a2[mi][ni];
                const float c00 = ((float)q1[0] + (float)q2[0] * (1.f / 254.f)) * (sa0 * sb0) + b0;
                const float c01 = ((float)q1[1] + (float)q2[1] * (1.f / 254.f)) * (sa0 * sb1) + b1;
                const float c10 = ((float)q1[2] + (float)q2[2] * (1.f / 254.f)) * (sa8 * sb0) + b0;
                const float c11 = ((float)q1[3] + (float)q2[3] * (1.f / 254.f)) * (sa8 * sb1) + b1;
                *(uint32_t*)(g_v16 + (size_t)m0 * DMODEL + n)       = h2u(c00, c01);
                *(uint32_t*)(g_v16 + (size_t)(m0 + 8) * DMODEL + n) = h2u(c10, c11);
            }
        }
    } else {
        int8_t* D1 = z ? g_k1 : g_q1;
        int8_t* D2 = z ? g_k2 : g_q2;
        float* sOut = z ? g_sk : g_sq;
        const float smul = z ? 1.0f : 0.125f * 1.44269504f;
        const int head = bn >> 6;

        float vv[2][2][8];
        float pmx[2][2];
        #pragma unroll
        for (int mi = 0; mi < 2; ++mi) {
            const int m0 = bm + wm0 + mi * 16 + erow;
            const float sa0 = sA[m0], sa8 = sA[m0 + 8];
            float mx0 = 0.f, mx1 = 0.f;
            #pragma unroll
            for (int ni = 0; ni < 4; ++ni) {
                const int n = bn + wn0 + ni * 8 + ecol;
                const float sb0 = __uint_as_float(sBbits[n])     * (1.f / 127.f);
                const float sb1 = __uint_as_float(sBbits[n + 1]) * (1.f / 127.f);
                const float b0 = bias[n], b1 = bias[n + 1];
                const int* q1 = acc.a1[mi][ni];
                const int* q2 = acc.a2[mi][ni];
                const float c00 = ((float)q1[0] + (float)q2[0] * (1.f / 254.f)) * (sa0 * sb0) + b0;
                const float c01 = ((float)q1[1] + (float)q2[1] * (1.f / 254.f)) * (sa0 * sb1) + b1;
                const float c10 = ((float)q1[2] + (float)q2[2] * (1.f / 254.f)) * (sa8 * sb0) + b0;
                const float c11 = ((float)q1[3] + (float)q2[3] * (1.f / 254.f)) * (sa8 * sb1) + b1;
                vv[mi][0][ni * 2 + 0] = c00;  vv[mi][0][ni * 2 + 1] = c01;
                vv[mi][1][ni * 2 + 0] = c10;  vv[mi][1][ni * 2 + 1] = c11;
                mx0 = fmaxf(mx0, fmaxf(fabsf(c00), fabsf(c01)));
                mx1 = fmaxf(mx1, fmaxf(fabsf(c10), fabsf(c11)));
            }
            mx0 = fmaxf(mx0, __shfl_xor_sync(0xffffffffu, mx0, 1));
            mx0 = fmaxf(mx0, __shfl_xor_sync(0xffffffffu, mx0, 2));
            mx1 = fmaxf(mx1, __shfl_xor_sync(0xffffffffu, mx1, 1));
            mx1 = fmaxf(mx1, __shfl_xor_sync(0xffffffffu, mx1, 2));
            pmx[mi][0] = mx0;
            pmx[mi][1] = mx1;
        }

        float* red = (float*)sm;
        if ((lane & 3) == 0) {
            #pragma unroll
            for (int mi = 0; mi < 2; ++mi) {
                red[(wm0 + mi * 16 + erow) * 2 + wn]     = pmx[mi][0];
                red[(wm0 + mi * 16 + erow + 8) * 2 + wn] = pmx[mi][1];
            }
        }
        __syncthreads();

        #pragma unroll
        for (int mi = 0; mi < 2; ++mi) {
            const int m0 = bm + wm0 + mi * 16 + erow;
            const int r0 = wm0 + mi * 16 + erow;
            const float mx0 = fmaxf(fmaxf(red[r0 * 2], red[r0 * 2 + 1]), 1e-20f);
            const float mx1 = fmaxf(fmaxf(red[(r0 + 8) * 2], red[(r0 + 8) * 2 + 1]), 1e-20f);
            if (wn == 0 && (lane & 3) == 0) {
                sOut[head * S_LEN + m0]     = mx0 * (smul / 127.f);
                sOut[head * S_LEN + m0 + 8] = mx1 * (smul / 127.f);
            }
            const float i0 = 127.f / mx0, i1 = 127.f / mx1;
            #pragma unroll
            for (int ni = 0; ni < 4; ++ni) {
                const int n = bn + wn0 + ni * 8 + ecol;
                uint32_t w2;
                uint32_t w1 = pack_dig(vv[mi][0][ni * 2] * i0, vv[mi][0][ni * 2 + 1] * i0, w2);
                *(uint16_t*)(D1 + (size_t)m0 * DMODEL + n) = (uint16_t)w1;
                *(uint16_t*)(D2 + (size_t)m0 * DMODEL + n) = (uint16_t)w2;
                w1 = pack_dig(vv[mi][1][ni * 2] * i1, vv[mi][1][ni * 2 + 1] * i1, w2);
                *(uint16_t*)(D1 + (size_t)(m0 + 8) * DMODEL + n) = (uint16_t)w1;
                *(uint16_t*)(D2 + (size_t)(m0 + 8) * DMODEL + n) = (uint16_t)w2;
            }
        }
    }
}

// O projection: fp32 out + bias, grid (16, 32), 2 CTAs/SM
__global__ __launch_bounds__(256, 2)
void gemm_o_kernel(const float* __restrict__ bias, float* __restrict__ C)
{
    extern __shared__ char sm[];
    const uint32_t sbase = smem_u32(sm);
    const int tid  = threadIdx.x;
    const int lane = tid & 31;
    const int wid  = tid >> 5;
    const int wm0  = (wid & 3) * 32;
    const int wn0  = (wid >> 2) * 32;
    const int bm   = blockIdx.y * 128;
    const int bn   = blockIdx.x * 64;

    GemmAcc acc;
    gemm_mainloop64(g_c1 + (size_t)bm * DMODEL, g_c2 + (size_t)bm * DMODEL,
                    g_wo1 + (size_t)bn * DMODEL, g_wo2 + (size_t)bn * DMODEL,
                    sbase, tid, lane, wm0, wn0, acc);

    const unsigned* sBbits = g_wbits + 3 * DMODEL;
    const int erow = lane >> 2;
    const int ecol = (lane & 3) * 2;
    #pragma unroll
    for (int mi = 0; mi < 2; ++mi) {
        const int m0 = bm + wm0 + mi * 16 + erow;
        const float sa0 = g_sc[m0], sa8 = g_sc[m0 + 8];
        #pragma unroll
        for (int ni = 0; ni < 4; ++ni) {
            const int n = bn + wn0 + ni * 8 + ecol;
            const float sb0 = __uint_as_float(sBbits[n])     * (1.f / 127.f);
            const float sb1 = __uint_as_float(sBbits[n + 1]) * (1.f / 127.f);
            const float b0 = bias[n], b1 = bias[n + 1];
            const int* q1 = acc.a1[mi][ni];
            const int* q2 = acc.a2[mi][ni];
            float2 v0, v1;
            v0.x = ((float)q1[0] + (float)q2[0] * (1.f / 254.f)) * (sa0 * sb0) + b0;
            v0.y = ((float)q1[1] + (float)q2[1] * (1.f / 254.f)) * (sa0 * sb1) + b1;
            v1.x = ((float)q1[2] + (float)q2[2] * (1.f / 254.f)) * (sa8 * sb0) + b0;
            v1.y = ((float)q1[3] + (float)q2[3] * (1.f / 254.f)) * (sa8 * sb1) + b1;
            *(float2*)(C + (size_t)m0 * DMODEL + n)       = v0;
            *(float2*)(C + (size_t)(m0 + 8) * DMODEL + n) = v1;
        }
    }
}

// ======================= hybrid flash attention =======================
// l computed via tensor pipe: V pad column 64 holds 1.0h, extra n=8 fp16 MMA.
#define AK_ROWB 80
#define AK_B (128 * AK_ROWB)
#define AV_ROWB 144
#define AV_B (128 * AV_ROWB)
#define ASK_OFF (2 * AK_B + AV_B)
#define ABUF_B (ASK_OFF + 512)
#define ATT_SMEM (2 * ABUF_B)

__global__ __launch_bounds__(256, 2)
void attn_kernel()
{
    extern __shared__ char sm[];
    const uint32_t sbase = smem_u32(sm);

    const int tid  = threadIdx.x;
    const int lane = tid & 31;
    const int w    = tid >> 5;
    const int h    = blockIdx.y;
    const int qt   = (int)gridDim.x - 1 - (int)blockIdx.x;
    const int q0   = qt * 128;
    const int hoff = h * DK;
    const int q0w  = q0 + w * 16;

    const int r  = lane >> 2;
    const int kc = (lane & 3) * 2;

    uint32_t q1f[2][4], q2f[2][4];
    {
        const int qb = (lane & 3) * 4;
        #pragma unroll
        for (int g = 0; g < 2; ++g) {
            const size_t bA = (size_t)(q0w + r) * DMODEL + hoff + g * 32 + qb;
            const size_t bB = (size_t)(q0w + r + 8) * DMODEL + hoff + g * 32 + qb;
            q1f[g][0] = *(const uint32_t*)(g_q1 + bA);
            q1f[g][1] = *(const uint32_t*)(g_q1 + bB);
            q1f[g][2] = *(const uint32_t*)(g_q1 + bA + 16);
            q1f[g][3] = *(const uint32_t*)(g_q1 + bB + 16);
            q2f[g][0] = *(const uint32_t*)(g_q2 + bA);
            q2f[g][1] = *(const uint32_t*)(g_q2 + bB);
            q2f[g][2] = *(const uint32_t*)(g_q2 + bA + 16);
            q2f[g][3] = *(const uint32_t*)(g_q2 + bB + 16);
        }
    }
    const float sq0f = g_sq[h * S_LEN + q0w + r]     * (1.f / 254.f);
    const float sq1f = g_sq[h * S_LEN + q0w + r + 8] * (1.f / 254.f);

    auto issue_kv = [&](int kt, int buf) {
        const int k0 = kt * 128;
        const uint32_t sb = sbase + buf * ABUF_B;
        #pragma unroll
        for (int d = 0; d < 2; ++d) {
            const int8_t* src = (d ? g_k2 : g_k1) + (size_t)k0 * DMODEL + hoff;
            #pragma unroll
            for (int j = 0; j < 2; ++j) {
                const int slot = tid + j * 256;
                const int row = slot >> 2, col = slot & 3;
                cp16(sb + d * AK_B + row * AK_ROWB + col * 16,
                     src + (size_t)row * DMODEL + col * 16);
            }
        }
        {
            const __half* src = g_v16 + (size_t)k0 * DMODEL + hoff;
            #pragma unroll
            for (int j = 0; j < 4; ++j) {
                const int slot = tid + j * 256;
                const int row = slot >> 3, col = slot & 7;
                cp16(sb + 2 * AK_B + row * AV_ROWB + col * 16,
                     src + (size_t)row * DMODEL + col * 8);
            }
        }
        if (tid < 32)
            cp16(sb + ASK_OFF + tid * 16, g_sk + h * S_LEN + k0 + tid * 4);
    };

    issue_kv(0, 0);
    cp_commit();

    // init V pad columns (col 64 = 1.0h, cols 65..71 = 0) for both buffers;
    // cp.async never touches these bytes.
    {
        const int bufi = tid >> 7, row = tid & 127;
        uint4 pv = make_uint4(0x00003C00u, 0u, 0u, 0u);
        *(uint4*)(sm + bufi * ABUF_B + 2 * AK_B + row * AV_ROWB + 128) = pv;
    }

    float m_[2] = { -1e30f, -1e30f };
    float oacc[8][4];
    float lacc[4] = { 0.f, 0.f, 0.f, 0.f };
    #pragma unroll
    for (int i = 0; i < 8; i++)
        #pragma unroll
        for (int j = 0; j < 4; j++) oacc[i][j] = 0.f;

    const uint32_t b_off  = (uint32_t)(((lane >> 4) << 3) + (lane & 7));
    const uint32_t kb_off = ((lane >> 3) & 1) * 16;
    const uint32_t vrow   = lane & 15;
    const uint32_t vcol   = (lane >> 4) * 8;

    for (int kt = 0; kt <= qt; ++kt) {
        const int buf = kt & 1;
        const bool hasNext = kt < qt;
        if (hasNext) { issue_kv(kt + 1, buf ^ 1); cp_commit(); }
        if (hasNext) cp_wait1(); else cp_wait0();
        __syncthreads();

        const uint32_t k1b = sbase + buf * ABUF_B;
        const uint32_t k2b = k1b + AK_B;
        const uint32_t v_b = k1b + 2 * AK_B;
        const float* sks = (const float*)(sm + buf * ABUF_B + ASK_OFF);

        #pragma unroll
        for (int half = 0; half < 2; ++half) {
            if (kt == qt && half == 1 && (w * 16 + 15) < 64) break;

            const int kbase = half * 64;

            float s[8][4];
            #pragma unroll
            for (int nt2 = 0; nt2 < 4; ++nt2) {
                int a1[2][4] = { {0,0,0,0}, {0,0,0,0} };
                int a2[2][4] = { {0,0,0,0}, {0,0,0,0} };
                #pragma unroll
                for (int g = 0; g < 2; ++g) {
                    const uint32_t addr = (uint32_t)(kbase + nt2 * 16 + b_off) * AK_ROWB + g * 32 + kb_off;
                    uint32_t fb1[4], fb2[4];
                    ldsm_x4(fb1, k1b + addr);
                    ldsm_x4(fb2, k2b + addr);
                    #pragma unroll
                    for (int hf = 0; hf < 2; ++hf) {
                        mma_s8(a1[hf], q1f[g], fb1 + hf * 2);
                        mma_s8(a2[hf], q1f[g], fb2 + hf * 2);
                        mma_s8(a2[hf], q2f[g], fb1 + hf * 2);
                    }
                }
                #pragma unroll
                for (int hf = 0; hf < 2; ++hf) {
                    const float2 sk2 = *(const float2*)(sks + (kbase + (nt2 * 2 + hf) * 8) + kc);
                    s[nt2 * 2 + hf][0] = (float)(a1[hf][0] * 254 + a2[hf][0]) * (sq0f * sk2.x);
                    s[nt2 * 2 + hf][1] = (float)(a1[hf][1] * 254 + a2[hf][1]) * (sq0f * sk2.y);
                    s[nt2 * 2 + hf][2] = (float)(a1[hf][2] * 254 + a2[hf][2]) * (sq1f * sk2.x);
                    s[nt2 * 2 + hf][3] = (float)(a1[hf][3] * 254 + a2[hf][3]) * (sq1f * sk2.y);
                }
            }

            if (kt == qt) {
                #pragma unroll
                for (int nt = 0; nt < 8; ++nt) {
                    #pragma unroll
                    for (int c = 0; c < 4; ++c) {
                        const int key = kbase + nt * 8 + kc + (c & 1);
                        const int qq  = w * 16 + r + (c >> 1) * 8;
                        if (key > qq) s[nt][c] = -1e30f;
                    }
                }
            }

            float mx0 = -1e30f, mx1 = -1e30f;
            #pragma unroll
            for (int nt = 0; nt < 8; ++nt) {
                mx0 = fmaxf(mx0, fmaxf(s[nt][0], s[nt][1]));
                mx1 = fmaxf(mx1, fmaxf(s[nt][2], s[nt][3]));
            }
            mx0 = fmaxf(mx0, __shfl_xor_sync(0xffffffffu, mx0, 1));
            mx0 = fmaxf(mx0, __shfl_xor_sync(0xffffffffu, mx0, 2));
            mx1 = fmaxf(mx1, __shfl_xor_sync(0xffffffffu, mx1, 1));
            mx1 = fmaxf(mx1, __shfl_xor_sync(0xffffffffu, mx1, 2));

            const bool upd = (mx0 > m_[0]) || (mx1 > m_[1]);
            if (__any_sync(0xffffffffu, upd)) {
                const float nm0 = fmaxf(m_[0], mx0), nm1 = fmaxf(m_[1], mx1);
                const float al0 = ex2f(m_[0] - nm0), al1 = ex2f(m_[1] - nm1);
                m_[0] = nm0;   m_[1] = nm1;
                lacc[0] *= al0;  lacc[2] *= al1;
                #pragma unroll
                for (int dt = 0; dt < 8; ++dt) {
                    oacc[dt][0] *= al0; oacc[dt][1] *= al0;
                    oacc[dt][2] *= al1; oacc[dt][3] *= al1;
                }
            }

            #pragma unroll
            for (int nt = 0; nt < 8; ++nt) {
                s[nt][0] = ex2f(s[nt][0] - m_[0]);
                s[nt][1] = ex2f(s[nt][1] - m_[0]);
                s[nt][2] = ex2f(s[nt][2] - m_[1]);
                s[nt][3] = ex2f(s[nt][3] - m_[1]);
            }

            #pragma unroll
            for (int j = 0; j < 4; ++j) {
                uint32_t pa[4];
                pa[0] = h2u(s[2*j][0],   s[2*j][1]);
                pa[1] = h2u(s[2*j][2],   s[2*j][3]);
                pa[2] = h2u(s[2*j+1][0], s[2*j+1][1]);
                pa[3] = h2u(s[2*j+1][2], s[2*j+1][3]);

                const uint32_t abase = (kbase + j * 16 + vrow) * AV_ROWB + vcol * 2;
                #pragma unroll
                for (int dg = 0; dg < 4; ++dg) {
                    uint32_t bv[4];
                    ldsm_x4_t(bv, v_b + abase + dg * 32);
                    mma_f16(oacc[dg * 2 + 0], pa, bv + 0);
                    mma_f16(oacc[dg * 2 + 1], pa, bv + 2);
                }
                // l += P @ ones  (V pad column 64)
                {
                    uint32_t bv[4];
                    ldsm_x4_t(bv, v_b + abase + 4 * 32);
                    mma_f16(lacc, pa, bv + 0);
                }
            }
        }
        __syncthreads();
    }

    // epilogue: broadcast l from quad root (col 64 holder), normalize, write ctx
    const float l0 = __shfl_sync(0xffffffffu, lacc[0], lane & ~3);
    const float l1 = __shfl_sync(0xffffffffu, lacc[2], lane & ~3);
    const float inv0 = 1.f / l0, inv1 = 1.f / l1;
    #pragma unroll
    for (int dt = 0; dt < 8; ++dt) {
        const size_t d = (size_t)hoff + dt * 8 + kc;
        const size_t rowA = (size_t)(q0w + r) * DMODEL + d;
        const size_t rowB = (size_t)(q0w + r + 8) * DMODEL + d;
        float2 a0 = { oacc[dt][0] * inv0, oacc[dt][1] * inv0 };
        float2 a1 = { oacc[dt][2] * inv1, oacc[dt][3] * inv1 };
        *(float2*)(g_ctx + rowA) = a0;
        *(float2*)(g_ctx + rowB) = a1;
    }
}

// ======================= host launcher =======================
extern "C" void kernel_launch(void* const* d_in, const int* in_sizes, int n_in,
                              void* d_out, int out_size)
{
    (void)in_sizes; (void)n_in; (void)out_size;
    const float* x  = (const float*)d_in[0];
    const float* Wq = (const float*)d_in[2];
    const float* bq = (const float*)d_in[3];
    const float* Wk = (const float*)d_in[4];
    const float* bk = (const float*)d_in[5];
    const float* Wv = (const float*)d_in[6];
    const float* bv = (const float*)d_in[7];
    const float* Wo = (const float*)d_in[8];
    const float* bo = (const float*)d_in[9];
    float* out = (float*)d_out;

    int8_t *c1, *c2;
    float *sc, *ctx;
    cudaGetSymbolAddress((void**)&c1, g_c1);
    cudaGetSymbolAddress((void**)&c2, g_c2);
    cudaGetSymbolAddress((void**)&sc, g_sc);
    cudaGetSymbolAddress((void**)&ctx, g_ctx);

    cudaFuncSetAttribute(gemm_qkv_kernel,
                         cudaFuncAttributeMaxDynamicSharedMemorySize, QGEMM_SMEM);
    cudaFuncSetAttribute(gemm_o_kernel,
                         cudaFuncAttributeMaxDynamicSharedMemorySize, QGEMM_SMEM);
    cudaFuncSetAttribute(attn_kernel,
                         cudaFuncAttributeMaxDynamicSharedMemorySize, ATT_SMEM);

    // 1: weight column max
    colmax4_kernel<<<dim3(8, 4), 1024>>>(Wq, Wk, Wv, Wo);
    // 2: weight transpose+quant + input rowquant (merged)
    prep_combo_kernel<<<dim3(32, 32, 8), 256>>>(Wq, Wk, Wv, Wo, x);
    // 3: fused Q/K/V projections
    gemm_qkv_kernel<<<dim3(16, 32, 3), 256, QGEMM_SMEM>>>(bq, bk, bv);
    // 4: attention  (profiled slot)
    attn_kernel<<<dim3(S_LEN / 128, NHEADS), 256, ATT_SMEM>>>();
    // 5: ctx row-quant
    rowquant_kernel<<<S_LEN, 256>>>(ctx, c1, c2, sc);
    // 6: O projection
    gemm_o_kernel<<<dim3(16, 32), 256, QGEMM_SMEM>>>(bo, out);
}